// round 2
// baseline (speedup 1.0000x reference)
#include <cuda_runtime.h>

#define EPS 1e-5f

// Problem constants (fixed by the dataset shapes)
#define B_  4
#define N_  512
#define M_  512
#define D_  128
#define H_  128

#define TN 8      // n rows per tile
#define TM 16     // m rows per tile
#define TP 128    // pairs per tile = TN*TM

// Scratch for the separable terms: xw = x@W1x + b1, yw = y@W1y  (b1 ONLY in xw)
__device__ float g_xw[B_ * N_ * H_];
__device__ float g_yw[B_ * M_ * H_];

// ---------------------------------------------------------------------------
// Kernel 1: precompute xw/yw. 512 blocks x 128 threads; 8 rows per block.
// ---------------------------------------------------------------------------
__global__ __launch_bounds__(128) void precompute_kernel(
    const float* __restrict__ x, const float* __restrict__ y,
    const float* __restrict__ W1, const float* __restrict__ b1)
{
    const bool isY = blockIdx.x >= 256;
    const int r0 = (isY ? blockIdx.x - 256 : blockIdx.x) * 8;  // global row (b*512+n)
    const float* __restrict__ src = isY ? y : x;
    const float* __restrict__ W = W1 + (isY ? D_ * H_ : 0);
    float* __restrict__ dst = isY ? g_yw : g_xw;

    __shared__ float v[8][D_];
    const int h = threadIdx.x;
    #pragma unroll
    for (int r = 0; r < 8; r++) v[r][h] = src[(r0 + r) * D_ + h];
    __syncthreads();

    float acc[8];
    const float bb = isY ? 0.f : b1[h];   // b1 added exactly once (in xw)
    #pragma unroll
    for (int r = 0; r < 8; r++) acc[r] = bb;

    #pragma unroll 4
    for (int d = 0; d < D_; d++) {
        const float w = W[d * H_ + h];
        #pragma unroll
        for (int r = 0; r < 8; r++) acc[r] = fmaf(v[r][d], w, acc[r]);
    }
    #pragma unroll
    for (int r = 0; r < 8; r++) dst[(r0 + r) * H_ + h] = acc[r];
}

// ---------------------------------------------------------------------------
// Kernel 2: main fused kernel.
// Per block: tile of TP=128 pairs (TN n's x TM m's) x H=128.
//  - generate A^T[d][p] = |x[n(p),d] - y[m(p),d]| in SMEM
//  - 8x8 register-blocked fp32 GEMM against W1d (SMEM-resident)
//  - fused epilogue: + xw + yw, layernorm over H, relu, dot W2, +b2, relu
// ---------------------------------------------------------------------------
#define SMEM_FLOATS (16384 + 16384 + 8*129 + 16*129 + 8*128 + 16*128 + 3*128)
#define SMEM_BYTES  (SMEM_FLOATS * 4)

__global__ __launch_bounds__(256, 1) void main_kernel(
    const float* __restrict__ x, const float* __restrict__ y,
    const float* __restrict__ W1,
    const float* __restrict__ gamma, const float* __restrict__ beta,
    const float* __restrict__ W2, const float* __restrict__ b2,
    float* __restrict__ out)
{
    extern __shared__ float sm[];
    float* Ws  = sm;                  // 16384
    float* As  = Ws + 16384;          // 16384 (reused as Cs)
    float* xs  = As + 16384;          // 8*129
    float* ys  = xs + 8 * 129;        // 16*129
    float* xws = ys + 16 * 129;       // 8*128
    float* yws = xws + 8 * 128;       // 16*128
    float* gam = yws + 16 * 128;      // 128
    float* bet = gam + 128;           // 128
    float* w2s = bet + 128;           // 128

    const int tid = threadIdx.x;
    const int b  = blockIdx.z;
    const int n0 = blockIdx.y * TN;
    const int m0 = blockIdx.x * TM;

    // ---- load W1d (rows 2D..3D of W1) as float4, coalesced ----
    {
        const float4* __restrict__ Wg = (const float4*)(W1 + 2 * D_ * H_);
        float4* Ws4 = (float4*)Ws;
        #pragma unroll
        for (int i = 0; i < 16; i++)
            Ws4[i * 256 + tid] = Wg[i * 256 + tid];
    }

    // ---- load x/y tiles (row stride 129 to kill A-gen bank conflicts) ----
    for (int i = tid; i < TN * D_; i += 256) {
        const int r = i >> 7, c = i & 127;
        xs[r * 129 + c] = x[(b * N_ + n0 + r) * D_ + c];
    }
    for (int i = tid; i < TM * D_; i += 256) {
        const int r = i >> 7, c = i & 127;
        ys[r * 129 + c] = y[(b * M_ + m0 + r) * D_ + c];
    }
    if (tid < 128) { gam[tid] = gamma[tid]; bet[tid] = beta[tid]; w2s[tid] = W2[tid]; }
    __syncthreads();

    // ---- generate A^T[d][p] = |x[p/16][d] - y[p%16][d]| ----
    #pragma unroll 4
    for (int i = 0; i < 64; i++) {
        const int e = i * 256 + tid;
        const int d = e >> 7, p = e & 127;
        As[d * 128 + p] = fabsf(xs[(p >> 4) * 129 + d] - ys[(p & 15) * 129 + d]);
    }
    __syncthreads();

    // ---- prefetch xw/yw tiles into SMEM (consumed only after next barrier) ----
    for (int i = tid; i < TN * H_; i += 256)
        xws[i] = g_xw[(b * N_ + n0 + (i >> 7)) * H_ + (i & 127)];
    for (int i = tid; i < TM * H_; i += 256)
        yws[i] = g_yw[(b * M_ + m0 + (i >> 7)) * H_ + (i & 127)];

    // ---- GEMM: 16x16 thread grid, 8 pairs x 8 h per thread ----
    const int p0 = (tid >> 4) * 8;
    const int h0 = (tid & 15) * 8;
    float acc[8][8];
    #pragma unroll
    for (int i = 0; i < 8; i++)
        #pragma unroll
        for (int j = 0; j < 8; j++) acc[i][j] = 0.f;

    #pragma unroll 4
    for (int k = 0; k < D_; k++) {
        float a[8], w[8];
        *(float4*)&a[0] = *(const float4*)&As[k * 128 + p0];
        *(float4*)&a[4] = *(const float4*)&As[k * 128 + p0 + 4];
        *(float4*)&w[0] = *(const float4*)&Ws[k * 128 + h0];
        *(float4*)&w[4] = *(const float4*)&Ws[k * 128 + h0 + 4];
        #pragma unroll
        for (int i = 0; i < 8; i++)
            #pragma unroll
            for (int j = 0; j < 8; j++)
                acc[i][j] = fmaf(a[i], w[j], acc[i][j]);
    }
    __syncthreads();   // everyone done reading As

    // ---- spill C tile to SMEM (reuse As) ----
    float* Cs = As;
    #pragma unroll
    for (int i = 0; i < 8; i++) {
        *(float4*)&Cs[(p0 + i) * 128 + h0]     = *(float4*)&acc[i][0];
        *(float4*)&Cs[(p0 + i) * 128 + h0 + 4] = *(float4*)&acc[i][4];
    }
    __syncthreads();

    // ---- epilogue: warp per row-group; 16 rows per warp ----
    const int warp = tid >> 5, lane = tid & 31;
    const float bb2 = b2[0];
    for (int rr = 0; rr < 16; rr++) {
        const int p = warp * 16 + rr;
        const int nl = p >> 4, ml = p & 15;
        float v[4], s = 0.f, s2 = 0.f;
        #pragma unroll
        for (int j = 0; j < 4; j++) {
            const int h = lane + j * 32;
            v[j] = Cs[p * 128 + h] + xws[nl * 128 + h] + yws[ml * 128 + h];
            s += v[j];
            s2 = fmaf(v[j], v[j], s2);
        }
        #pragma unroll
        for (int o = 16; o; o >>= 1) {
            s  += __shfl_xor_sync(0xffffffffu, s, o);
            s2 += __shfl_xor_sync(0xffffffffu, s2, o);
        }
        const float mu  = s * (1.f / 128.f);
        const float var = s2 * (1.f / 128.f) - mu * mu;
        const float rs  = rsqrtf(var + EPS);
        float o2 = 0.f;
        #pragma unroll
        for (int j = 0; j < 4; j++) {
            const int h = lane + j * 32;
            const float t = fmaf((v[j] - mu) * rs, gam[h], bet[h]);
            o2 = fmaf(fmaxf(t, 0.f), w2s[h], o2);
        }
        #pragma unroll
        for (int o = 16; o; o >>= 1)
            o2 += __shfl_xor_sync(0xffffffffu, o2, o);
        if (lane == 0)
            out[(b * N_ + n0 + nl) * M_ + m0 + ml] = fmaxf(o2 + bb2, 0.f);
    }
}

// ---------------------------------------------------------------------------
extern "C" void kernel_launch(void* const* d_in, const int* in_sizes, int n_in,
                              void* d_out, int out_size)
{
    const float* x     = (const float*)d_in[0];
    const float* y     = (const float*)d_in[1];
    const float* W1    = (const float*)d_in[2];
    const float* b1    = (const float*)d_in[3];
    const float* gamma = (const float*)d_in[4];
    const float* beta  = (const float*)d_in[5];
    const float* W2    = (const float*)d_in[6];
    const float* b2    = (const float*)d_in[7];
    float* out = (float*)d_out;

    cudaFuncSetAttribute(main_kernel,
                         cudaFuncAttributeMaxDynamicSharedMemorySize, SMEM_BYTES);

    precompute_kernel<<<512, 128>>>(x, y, W1, b1);

    dim3 grid(M_ / TM, N_ / TN, B_);
    main_kernel<<<grid, 256, SMEM_BYTES>>>(x, y, W1, gamma, beta, W2, b2, out);
}

// round 4
// speedup vs baseline: 5.2339x; 5.2339x over previous
#include <cuda_runtime.h>
#include <cuda_fp16.h>
#include <cstdint>

#define EPS 1e-5f
#define B_  4
#define N_  512
#define M_  512
#define D_  128
#define H_  128
#define TN 8
#define TM 16
#define NTILES 8192          // 4 * 64 * 32
#define GRID 148
#define THREADS 256

// SMEM byte offsets
#define SM_W    0                      // fp16 W1d^T [h][k], swizzled, 32768 B
#define SM_XS   32768                  // 2 x 8*128*4   = 2 x 4096
#define SM_YS   (SM_XS + 8192)         // 2 x 16*136*4  = 2 x 8704
#define SM_XWS  (SM_YS + 17408)        // 2 x 4096
#define SM_YWS  (SM_XWS + 8192)        // 2 x 8704
#define SM_GAM  (SM_YWS + 17408)
#define SM_BET  (SM_GAM + 512)
#define SM_W2   (SM_BET + 512)
#define SMEM_BYTES (SM_W2 + 512)

#define YSTRIDE 136   // floats per y-row (bank-conflict-free for (q,c) access)

__device__ __forceinline__ uint32_t smem_u32(const void* p) {
    uint32_t a;
    asm("{ .reg .u64 t; cvta.to.shared.u64 t, %1; cvt.u32.u64 %0, t; }" : "=r"(a) : "l"(p));
    return a;
}
__device__ __forceinline__ void ldsm4(uint32_t* r, uint32_t addr) {
    asm volatile("ldmatrix.sync.aligned.m8n8.x4.shared.b16 {%0,%1,%2,%3}, [%4];"
        : "=r"(r[0]), "=r"(r[1]), "=r"(r[2]), "=r"(r[3]) : "r"(addr));
}
__device__ __forceinline__ void mma16816(float* c, const uint32_t* a,
                                         uint32_t b0, uint32_t b1) {
    asm volatile("mma.sync.aligned.m16n8k16.row.col.f32.f16.f16.f32 "
        "{%0,%1,%2,%3}, {%4,%5,%6,%7}, {%8,%9}, {%0,%1,%2,%3};"
        : "+f"(c[0]), "+f"(c[1]), "+f"(c[2]), "+f"(c[3])
        : "r"(a[0]), "r"(a[1]), "r"(a[2]), "r"(a[3]), "r"(b0), "r"(b1));
}
// swizzled offset into a [rows][128] fp16 tile (256 B/row, 16B-chunk XOR swizzle)
__device__ __forceinline__ uint32_t woff(int r, int k) {
    return (uint32_t)(r * 256 + ((((k >> 3) ^ (r & 7)) << 4)) + (k & 7) * 2);
}
__device__ __forceinline__ uint32_t h2u(__half2 h) {
    return *reinterpret_cast<uint32_t*>(&h);
}

// Scratch: xw = x@W1x + b1 (b1 ONLY here), yw = y@W1y
__device__ float g_xw[B_ * N_ * H_];
__device__ float g_yw[B_ * M_ * H_];

// ---------------------------------------------------------------------------
// Kernel 1: precompute xw/yw (fp32 exact)
// ---------------------------------------------------------------------------
__global__ __launch_bounds__(128) void precompute_kernel(
    const float* __restrict__ x, const float* __restrict__ y,
    const float* __restrict__ W1, const float* __restrict__ b1)
{
    const bool isY = blockIdx.x >= 256;
    const int r0 = (isY ? blockIdx.x - 256 : blockIdx.x) * 8;
    const float* __restrict__ src = isY ? y : x;
    const float* __restrict__ W = W1 + (isY ? D_ * H_ : 0);
    float* __restrict__ dst = isY ? g_yw : g_xw;

    __shared__ float v[8][D_];
    const int h = threadIdx.x;
    #pragma unroll
    for (int r = 0; r < 8; r++) v[r][h] = src[(r0 + r) * D_ + h];
    __syncthreads();

    float acc[8];
    const float bb = isY ? 0.f : b1[h];
    #pragma unroll
    for (int r = 0; r < 8; r++) acc[r] = bb;
    #pragma unroll 4
    for (int d = 0; d < D_; d++) {
        const float w = W[d * H_ + h];
        #pragma unroll
        for (int r = 0; r < 8; r++) acc[r] = fmaf(v[r][d], w, acc[r]);
    }
    #pragma unroll
    for (int r = 0; r < 8; r++) dst[(r0 + r) * H_ + h] = acc[r];
}

// ---------------------------------------------------------------------------
// Kernel 2: persistent HMMA kernel.
// Tile = 128 pairs (8n x 16m) x 128 h, K = 128.
// D = Ahi(f16)*W(f16) + Alo(f16)*W(f16), fp32 accum in registers.
// ---------------------------------------------------------------------------
__global__ void __launch_bounds__(THREADS, 1) main_kernel(
    const float* __restrict__ x, const float* __restrict__ y,
    const float* __restrict__ W1,
    const float* __restrict__ gamma, const float* __restrict__ beta,
    const float* __restrict__ W2, const float* __restrict__ b2,
    float* __restrict__ out)
{
    extern __shared__ char sm[];
    const int tid = threadIdx.x;
    const int wid = tid >> 5, lane = tid & 31;
    const int q = lane >> 2, c = lane & 3;

    // ---- one-time: W1d -> fp16 Wsm[h][k] swizzled ----
    {
        __half* wp = (__half*)sm;
        #pragma unroll
        for (int i = 0; i < 64; i++) {
            int e = i * 256 + tid;
            int k = e >> 7, h = e & 127;
            float v = W1[(2 * D_ + k) * H_ + h];
            *reinterpret_cast<__half*>((char*)wp + woff(h, k)) = __float2half_rn(v);
        }
    }
    if (tid < 128) {
        ((float*)(sm + SM_GAM))[tid] = gamma[tid];
        ((float*)(sm + SM_BET))[tid] = beta[tid];
        ((float*)(sm + SM_W2))[tid]  = W2[tid];
    }
    const float bias2 = b2[0];

    // per-lane ldmatrix B addressing constants
    const uint32_t wbase = smem_u32(sm);
    const int rp  = (((lane >> 4) & 1) << 3) + (lane & 7); // row within nt2 pair
    const int kb8 = (lane >> 3) & 1;                        // +8 k offset selector
    const int l7  = lane & 7;

    // tile loader (LDG + STS); safe to call while other buffer is in use
    auto load_tile = [&](int t, int sb) {
        const int bt = t >> 11, rem = t & 2047;
        const int n0 = (rem >> 5) * TN, m0 = (rem & 31) * TM;
        const float4* xg  = (const float4*)(x + (bt * N_ + n0) * D_);
        const float4* xwg = (const float4*)(g_xw + (bt * N_ + n0) * H_);
        float4* xsb  = (float4*)(sm + SM_XS  + sb * 4096);
        float4* xwsb = (float4*)(sm + SM_XWS + sb * 4096);
        xsb[tid]  = xg[tid];
        xwsb[tid] = xwg[tid];
        const float* yg  = y + (bt * M_ + m0) * D_;
        const float* ywg = g_yw + (bt * M_ + m0) * H_;
        float* ysb  = (float*)(sm + SM_YS  + sb * 8704);
        float* ywsb = (float*)(sm + SM_YWS + sb * 8704);
        #pragma unroll
        for (int j = 0; j < 2; j++) {
            int e = j * 256 + tid;
            int r = e >> 5, c4 = (e & 31) * 4;
            *(float4*)(ysb  + r * YSTRIDE + c4) = *(const float4*)(yg  + r * 128 + c4);
            *(float4*)(ywsb + r * YSTRIDE + c4) = *(const float4*)(ywg + r * 128 + c4);
        }
    };

    load_tile(blockIdx.x, 0);
    __syncthreads();

    int iter = 0;
    for (int t = blockIdx.x; t < NTILES; t += GRID, iter++) {
        const int sb = iter & 1;
        const int bt = t >> 11, rem = t & 2047;
        const int n0 = (rem >> 5) * TN, m0 = (rem & 31) * TM;

        // ---- A-gen: |x - y| -> fp16 hi/lo fragments in registers ----
        uint32_t ahi[8][4], alo[8][4];
        {
            const float* xr  = (const float*)(sm + SM_XS + sb * 4096) + wid * 128;
            const float* yra = (const float*)(sm + SM_YS + sb * 8704) + q * YSTRIDE;
            const float* yrb = yra + 8 * YSTRIDE;
            #pragma unroll
            for (int kt = 0; kt < 8; kt++) {
                const int k0 = kt * 16 + 2 * c;
                float2 x0 = *(const float2*)(xr + k0);
                float2 x1 = *(const float2*)(xr + k0 + 8);
                float2 a0 = *(const float2*)(yra + k0);
                float2 a1 = *(const float2*)(yra + k0 + 8);
                float2 b0 = *(const float2*)(yrb + k0);
                float2 b1 = *(const float2*)(yrb + k0 + 8);
                float d00 = fabsf(x0.x - a0.x), d01 = fabsf(x0.y - a0.y);
                float d10 = fabsf(x0.x - b0.x), d11 = fabsf(x0.y - b0.y);
                float d20 = fabsf(x1.x - a1.x), d21 = fabsf(x1.y - a1.y);
                float d30 = fabsf(x1.x - b1.x), d31 = fabsf(x1.y - b1.y);
                __half2 h0 = __floats2half2_rn(d00, d01);
                __half2 h1 = __floats2half2_rn(d10, d11);
                __half2 h2 = __floats2half2_rn(d20, d21);
                __half2 h3 = __floats2half2_rn(d30, d31);
                float2 f0 = __half22float2(h0);
                float2 f1 = __half22float2(h1);
                float2 f2 = __half22float2(h2);
                float2 f3 = __half22float2(h3);
                ahi[kt][0] = h2u(h0); ahi[kt][1] = h2u(h1);
                ahi[kt][2] = h2u(h2); ahi[kt][3] = h2u(h3);
                alo[kt][0] = h2u(__floats2half2_rn(d00 - f0.x, d01 - f0.y));
                alo[kt][1] = h2u(__floats2half2_rn(d10 - f1.x, d11 - f1.y));
                alo[kt][2] = h2u(__floats2half2_rn(d20 - f2.x, d21 - f2.y));
                alo[kt][3] = h2u(__floats2half2_rn(d30 - f3.x, d31 - f3.y));
            }
        }

        // ---- MMA mainloop ----
        float acc[16][4];
        #pragma unroll
        for (int i = 0; i < 16; i++)
            #pragma unroll
            for (int j = 0; j < 4; j++) acc[i][j] = 0.f;

        #pragma unroll
        for (int kt = 0; kt < 8; kt++) {
            uint32_t br[8][4];
            #pragma unroll
            for (int nt2 = 0; nt2 < 8; nt2++) {
                uint32_t addr = wbase + (uint32_t)((nt2 * 16 + rp) * 256)
                              + (uint32_t)((((2 * kt + kb8) ^ l7) << 4));
                ldsm4(br[nt2], addr);
            }
            #pragma unroll
            for (int nt2 = 0; nt2 < 8; nt2++) {
                mma16816(acc[2*nt2],   ahi[kt], br[nt2][0], br[nt2][1]);
                mma16816(acc[2*nt2+1], ahi[kt], br[nt2][2], br[nt2][3]);
            }
            #pragma unroll
            for (int nt2 = 0; nt2 < 8; nt2++) {
                mma16816(acc[2*nt2],   alo[kt], br[nt2][0], br[nt2][1]);
                mma16816(acc[2*nt2+1], alo[kt], br[nt2][2], br[nt2][3]);
            }
        }

        // ---- prefetch next tile (other buffer) ----
        if (t + GRID < NTILES) load_tile(t + GRID, sb ^ 1);

        // ---- epilogue: + xw + yw, LN over h, relu, dot W2, relu, store ----
        {
            const float* xwr = (const float*)(sm + SM_XWS + sb * 4096) + wid * 128;
            const float* ywa = (const float*)(sm + SM_YWS + sb * 8704) + q * YSTRIDE;
            const float* ywb = ywa + 8 * YSTRIDE;
            float s1a = 0.f, s2a = 0.f, s1b = 0.f, s2b = 0.f;
            #pragma unroll
            for (int nt = 0; nt < 16; nt++) {
                const int h = nt * 8 + 2 * c;
                float2 xw2 = *(const float2*)(xwr + h);
                float2 ya2 = *(const float2*)(ywa + h);
                float2 yb2 = *(const float2*)(ywb + h);
                float va0 = acc[nt][0] + xw2.x + ya2.x;
                float va1 = acc[nt][1] + xw2.y + ya2.y;
                float vb0 = acc[nt][2] + xw2.x + yb2.x;
                float vb1 = acc[nt][3] + xw2.y + yb2.y;
                acc[nt][0] = va0; acc[nt][1] = va1;
                acc[nt][2] = vb0; acc[nt][3] = vb1;
                s1a += va0 + va1; s2a = fmaf(va0, va0, fmaf(va1, va1, s2a));
                s1b += vb0 + vb1; s2b = fmaf(vb0, vb0, fmaf(vb1, vb1, s2b));
            }
            #pragma unroll
            for (int o = 1; o <= 2; o <<= 1) {
                s1a += __shfl_xor_sync(0xffffffffu, s1a, o);
                s2a += __shfl_xor_sync(0xffffffffu, s2a, o);
                s1b += __shfl_xor_sync(0xffffffffu, s1b, o);
                s2b += __shfl_xor_sync(0xffffffffu, s2b, o);
            }
            const float mua = s1a * (1.f / 128.f);
            const float mub = s1b * (1.f / 128.f);
            const float rsa = rsqrtf(s2a * (1.f / 128.f) - mua * mua + EPS);
            const float rsb = rsqrtf(s2b * (1.f / 128.f) - mub * mub + EPS);
            const float* gm  = (const float*)(sm + SM_GAM);
            const float* be  = (const float*)(sm + SM_BET);
            const float* w2s = (const float*)(sm + SM_W2);
            float oa = 0.f, ob = 0.f;
            #pragma unroll
            for (int nt = 0; nt < 16; nt++) {
                const int h = nt * 8 + 2 * c;
                float2 g2  = *(const float2*)(gm + h);
                float2 be2 = *(const float2*)(be + h);
                float2 w22 = *(const float2*)(w2s + h);
                float tv;
                tv = fmaf((acc[nt][0] - mua) * rsa, g2.x, be2.x);
                oa = fmaf(fmaxf(tv, 0.f), w22.x, oa);
                tv = fmaf((acc[nt][1] - mua) * rsa, g2.y, be2.y);
                oa = fmaf(fmaxf(tv, 0.f), w22.y, oa);
                tv = fmaf((acc[nt][2] - mub) * rsb, g2.x, be2.x);
                ob = fmaf(fmaxf(tv, 0.f), w22.x, ob);
                tv = fmaf((acc[nt][3] - mub) * rsb, g2.y, be2.y);
                ob = fmaf(fmaxf(tv, 0.f), w22.y, ob);
            }
            #pragma unroll
            for (int o = 1; o <= 2; o <<= 1) {
                oa += __shfl_xor_sync(0xffffffffu, oa, o);
                ob += __shfl_xor_sync(0xffffffffu, ob, o);
            }
            if (c == 0) {
                const int row = (bt * N_ + n0 + wid) * M_ + m0;
                out[row + q]     = fmaxf(oa + bias2, 0.f);
                out[row + q + 8] = fmaxf(ob + bias2, 0.f);
            }
        }

        __syncthreads();   // all reads of buf[sb] done; prefetch STS visible
    }
}

// ---------------------------------------------------------------------------
extern "C" void kernel_launch(void* const* d_in, const int* in_sizes, int n_in,
                              void* d_out, int out_size)
{
    const float* x     = (const float*)d_in[0];
    const float* y     = (const float*)d_in[1];
    const float* W1    = (const float*)d_in[2];
    const float* b1    = (const float*)d_in[3];
    const float* gamma = (const float*)d_in[4];
    const float* beta  = (const float*)d_in[5];
    const float* W2    = (const float*)d_in[6];
    const float* b2    = (const float*)d_in[7];
    float* out = (float*)d_out;

    cudaFuncSetAttribute(main_kernel,
                         cudaFuncAttributeMaxDynamicSharedMemorySize, SMEM_BYTES);

    precompute_kernel<<<512, 128>>>(x, y, W1, b1);
    main_kernel<<<GRID, THREADS, SMEM_BYTES>>>(x, y, W1, gamma, beta, W2, b2, out);
}

// round 5
// speedup vs baseline: 6.6921x; 1.2786x over previous
#include <cuda_runtime.h>
#include <cuda_fp16.h>
#include <cstdint>

#define EPS 1e-5f
#define B_  4
#define N_  512
#define M_  512
#define D_  128
#define H_  128
#define TN 8
#define TM 16
#define NTILES 8192          // 4 * 64 * 32
#define GRID 148
#define THREADS 256

// SMEM byte offsets
#define SM_W    0                      // fp16 W1d^T [h][k], swizzled, 32768 B
#define SM_XS   32768                  // 2 x 8*128*4   = 2 x 4096
#define SM_YS   (SM_XS + 8192)         // 2 x 16*136*4  = 2 x 8704
#define SM_XWS  (SM_YS + 17408)        // 2 x 4096
#define SM_YWS  (SM_XWS + 8192)        // 2 x 8704
#define SM_GAM  (SM_YWS + 17408)
#define SM_BET  (SM_GAM + 512)
#define SM_W2   (SM_BET + 512)
#define SMEM_BYTES (SM_W2 + 512)

#define YSTRIDE 136   // floats per y-row (bank-conflict-free for (q,c) access)

__device__ __forceinline__ uint32_t smem_u32(const void* p) {
    uint32_t a;
    asm("{ .reg .u64 t; cvta.to.shared.u64 t, %1; cvt.u32.u64 %0, t; }" : "=r"(a) : "l"(p));
    return a;
}
__device__ __forceinline__ void ldsm4(uint32_t* r, uint32_t addr) {
    asm volatile("ldmatrix.sync.aligned.m8n8.x4.shared.b16 {%0,%1,%2,%3}, [%4];"
        : "=r"(r[0]), "=r"(r[1]), "=r"(r[2]), "=r"(r[3]) : "r"(addr));
}
__device__ __forceinline__ void mma16816(float* c, const uint32_t* a,
                                         uint32_t b0, uint32_t b1) {
    asm volatile("mma.sync.aligned.m16n8k16.row.col.f32.f16.f16.f32 "
        "{%0,%1,%2,%3}, {%4,%5,%6,%7}, {%8,%9}, {%0,%1,%2,%3};"
        : "+f"(c[0]), "+f"(c[1]), "+f"(c[2]), "+f"(c[3])
        : "r"(a[0]), "r"(a[1]), "r"(a[2]), "r"(a[3]), "r"(b0), "r"(b1));
}
// swizzled offset into a [rows][128] fp16 tile (256 B/row, 16B-chunk XOR swizzle)
__device__ __forceinline__ uint32_t woff(int r, int k) {
    return (uint32_t)(r * 256 + ((((k >> 3) ^ (r & 7)) << 4)) + (k & 7) * 2);
}
__device__ __forceinline__ uint32_t h2u(__half2 h) {
    return *reinterpret_cast<uint32_t*>(&h);
}

// Scratch: xw = x@W1x + b1 (b1 ONLY here), yw = y@W1y
__device__ float g_xw[B_ * N_ * H_];
__device__ float g_yw[B_ * M_ * H_];

// ---------------------------------------------------------------------------
// Kernel 1: precompute xw/yw (fp32 exact)
// ---------------------------------------------------------------------------
__global__ __launch_bounds__(128) void precompute_kernel(
    const float* __restrict__ x, const float* __restrict__ y,
    const float* __restrict__ W1, const float* __restrict__ b1)
{
    const bool isY = blockIdx.x >= 256;
    const int r0 = (isY ? blockIdx.x - 256 : blockIdx.x) * 8;
    const float* __restrict__ src = isY ? y : x;
    const float* __restrict__ W = W1 + (isY ? D_ * H_ : 0);
    float* __restrict__ dst = isY ? g_yw : g_xw;

    __shared__ float v[8][D_];
    const int h = threadIdx.x;
    #pragma unroll
    for (int r = 0; r < 8; r++) v[r][h] = src[(r0 + r) * D_ + h];
    __syncthreads();

    float acc[8];
    const float bb = isY ? 0.f : b1[h];
    #pragma unroll
    for (int r = 0; r < 8; r++) acc[r] = bb;
    #pragma unroll 4
    for (int d = 0; d < D_; d++) {
        const float w = W[d * H_ + h];
        #pragma unroll
        for (int r = 0; r < 8; r++) acc[r] = fmaf(v[r][d], w, acc[r]);
    }
    #pragma unroll
    for (int r = 0; r < 8; r++) dst[(r0 + r) * H_ + h] = acc[r];
}

// ---------------------------------------------------------------------------
// Kernel 2: persistent HMMA kernel.
// Tile = 128 pairs (8n x 16m) x 128 h, K = 128.
// D = A(f16)*W(f16), fp32 accum in registers. Single-term A (fp16 rounding
// of |x-y| contributes ~2.4e-4 rel, same class as the W fp16 error).
// ---------------------------------------------------------------------------
__global__ void __launch_bounds__(THREADS, 1) main_kernel(
    const float* __restrict__ x, const float* __restrict__ y,
    const float* __restrict__ W1,
    const float* __restrict__ gamma, const float* __restrict__ beta,
    const float* __restrict__ W2, const float* __restrict__ b2,
    float* __restrict__ out)
{
    extern __shared__ char sm[];
    const int tid = threadIdx.x;
    const int wid = tid >> 5, lane = tid & 31;
    const int q = lane >> 2, c = lane & 3;

    // ---- one-time: W1d -> fp16 Wsm[h][k] swizzled ----
    {
        __half* wp = (__half*)sm;
        #pragma unroll
        for (int i = 0; i < 64; i++) {
            int e = i * 256 + tid;
            int k = e >> 7, h = e & 127;
            float v = W1[(2 * D_ + k) * H_ + h];
            *reinterpret_cast<__half*>((char*)wp + woff(h, k)) = __float2half_rn(v);
        }
    }
    if (tid < 128) {
        ((float*)(sm + SM_GAM))[tid] = gamma[tid];
        ((float*)(sm + SM_BET))[tid] = beta[tid];
        ((float*)(sm + SM_W2))[tid]  = W2[tid];
    }
    const float bias2 = b2[0];

    // per-lane ldmatrix B addressing constants
    const uint32_t wbase = smem_u32(sm);
    const int rp  = (((lane >> 4) & 1) << 3) + (lane & 7); // row within nt2 pair
    const int kb8 = (lane >> 3) & 1;                        // +8 k offset selector
    const int l7  = lane & 7;

    // tile loader (LDG + STS); safe to call while other buffer is in use
    auto load_tile = [&](int t, int sb) {
        const int bt = t >> 11, rem = t & 2047;
        const int n0 = (rem >> 5) * TN, m0 = (rem & 31) * TM;
        const float4* xg  = (const float4*)(x + (bt * N_ + n0) * D_);
        const float4* xwg = (const float4*)(g_xw + (bt * N_ + n0) * H_);
        float4* xsb  = (float4*)(sm + SM_XS  + sb * 4096);
        float4* xwsb = (float4*)(sm + SM_XWS + sb * 4096);
        xsb[tid]  = xg[tid];
        xwsb[tid] = xwg[tid];
        const float* yg  = y + (bt * M_ + m0) * D_;
        const float* ywg = g_yw + (bt * M_ + m0) * H_;
        float* ysb  = (float*)(sm + SM_YS  + sb * 8704);
        float* ywsb = (float*)(sm + SM_YWS + sb * 8704);
        #pragma unroll
        for (int j = 0; j < 2; j++) {
            int e = j * 256 + tid;
            int r = e >> 5, c4 = (e & 31) * 4;
            *(float4*)(ysb  + r * YSTRIDE + c4) = *(const float4*)(yg  + r * 128 + c4);
            *(float4*)(ywsb + r * YSTRIDE + c4) = *(const float4*)(ywg + r * 128 + c4);
        }
    };

    load_tile(blockIdx.x, 0);
    __syncthreads();

    int iter = 0;
    for (int t = blockIdx.x; t < NTILES; t += GRID, iter++) {
        const int sb = iter & 1;
        const int bt = t >> 11, rem = t & 2047;
        const int n0 = (rem >> 5) * TN, m0 = (rem & 31) * TM;

        // ---- A-gen: |x - y| -> fp16 fragments in registers ----
        uint32_t af[8][4];
        {
            const float* xr  = (const float*)(sm + SM_XS + sb * 4096) + wid * 128;
            const float* yra = (const float*)(sm + SM_YS + sb * 8704) + q * YSTRIDE;
            const float* yrb = yra + 8 * YSTRIDE;
            #pragma unroll
            for (int kt = 0; kt < 8; kt++) {
                const int k0 = kt * 16 + 2 * c;
                float2 x0 = *(const float2*)(xr + k0);
                float2 x1 = *(const float2*)(xr + k0 + 8);
                float2 a0 = *(const float2*)(yra + k0);
                float2 a1 = *(const float2*)(yra + k0 + 8);
                float2 b0 = *(const float2*)(yrb + k0);
                float2 b1 = *(const float2*)(yrb + k0 + 8);
                af[kt][0] = h2u(__floats2half2_rn(fabsf(x0.x - a0.x), fabsf(x0.y - a0.y)));
                af[kt][1] = h2u(__floats2half2_rn(fabsf(x0.x - b0.x), fabsf(x0.y - b0.y)));
                af[kt][2] = h2u(__floats2half2_rn(fabsf(x1.x - a1.x), fabsf(x1.y - a1.y)));
                af[kt][3] = h2u(__floats2half2_rn(fabsf(x1.x - b1.x), fabsf(x1.y - b1.y)));
            }
        }

        // ---- MMA mainloop ----
        float acc[16][4];
        #pragma unroll
        for (int i = 0; i < 16; i++)
            #pragma unroll
            for (int j = 0; j < 4; j++) acc[i][j] = 0.f;

        #pragma unroll
        for (int kt = 0; kt < 8; kt++) {
            uint32_t br[8][4];
            #pragma unroll
            for (int nt2 = 0; nt2 < 8; nt2++) {
                uint32_t addr = wbase + (uint32_t)((nt2 * 16 + rp) * 256)
                              + (uint32_t)((((2 * kt + kb8) ^ l7) << 4));
                ldsm4(br[nt2], addr);
            }
            #pragma unroll
            for (int nt2 = 0; nt2 < 8; nt2++) {
                mma16816(acc[2*nt2],   af[kt], br[nt2][0], br[nt2][1]);
                mma16816(acc[2*nt2+1], af[kt], br[nt2][2], br[nt2][3]);
            }
        }

        // ---- prefetch next tile (other buffer) ----
        if (t + GRID < NTILES) load_tile(t + GRID, sb ^ 1);

        // ---- epilogue: + xw + yw, LN over h, relu, dot W2, relu, store ----
        {
            const float* xwr = (const float*)(sm + SM_XWS + sb * 4096) + wid * 128;
            const float* ywa = (const float*)(sm + SM_YWS + sb * 8704) + q * YSTRIDE;
            const float* ywb = ywa + 8 * YSTRIDE;
            float s1a = 0.f, s2a = 0.f, s1b = 0.f, s2b = 0.f;
            #pragma unroll
            for (int nt = 0; nt < 16; nt++) {
                const int h = nt * 8 + 2 * c;
                float2 xw2 = *(const float2*)(xwr + h);
                float2 ya2 = *(const float2*)(ywa + h);
                float2 yb2 = *(const float2*)(ywb + h);
                float va0 = acc[nt][0] + xw2.x + ya2.x;
                float va1 = acc[nt][1] + xw2.y + ya2.y;
                float vb0 = acc[nt][2] + xw2.x + yb2.x;
                float vb1 = acc[nt][3] + xw2.y + yb2.y;
                acc[nt][0] = va0; acc[nt][1] = va1;
                acc[nt][2] = vb0; acc[nt][3] = vb1;
                s1a += va0 + va1; s2a = fmaf(va0, va0, fmaf(va1, va1, s2a));
                s1b += vb0 + vb1; s2b = fmaf(vb0, vb0, fmaf(vb1, vb1, s2b));
            }
            #pragma unroll
            for (int o = 1; o <= 2; o <<= 1) {
                s1a += __shfl_xor_sync(0xffffffffu, s1a, o);
                s2a += __shfl_xor_sync(0xffffffffu, s2a, o);
                s1b += __shfl_xor_sync(0xffffffffu, s1b, o);
                s2b += __shfl_xor_sync(0xffffffffu, s2b, o);
            }
            const float mua = s1a * (1.f / 128.f);
            const float mub = s1b * (1.f / 128.f);
            const float rsa = rsqrtf(s2a * (1.f / 128.f) - mua * mua + EPS);
            const float rsb = rsqrtf(s2b * (1.f / 128.f) - mub * mub + EPS);
            const float* gm  = (const float*)(sm + SM_GAM);
            const float* be  = (const float*)(sm + SM_BET);
            const float* w2s = (const float*)(sm + SM_W2);
            float oa = 0.f, ob = 0.f;
            #pragma unroll
            for (int nt = 0; nt < 16; nt++) {
                const int h = nt * 8 + 2 * c;
                float2 g2  = *(const float2*)(gm + h);
                float2 be2 = *(const float2*)(be + h);
                float2 w22 = *(const float2*)(w2s + h);
                float tv;
                tv = fmaf((acc[nt][0] - mua) * rsa, g2.x, be2.x);
                oa = fmaf(fmaxf(tv, 0.f), w22.x, oa);
                tv = fmaf((acc[nt][1] - mua) * rsa, g2.y, be2.y);
                oa = fmaf(fmaxf(tv, 0.f), w22.y, oa);
                tv = fmaf((acc[nt][2] - mub) * rsb, g2.x, be2.x);
                ob = fmaf(fmaxf(tv, 0.f), w22.x, ob);
                tv = fmaf((acc[nt][3] - mub) * rsb, g2.y, be2.y);
                ob = fmaf(fmaxf(tv, 0.f), w22.y, ob);
            }
            #pragma unroll
            for (int o = 1; o <= 2; o <<= 1) {
                oa += __shfl_xor_sync(0xffffffffu, oa, o);
                ob += __shfl_xor_sync(0xffffffffu, ob, o);
            }
            if (c == 0) {
                const int row = (bt * N_ + n0 + wid) * M_ + m0;
                out[row + q]     = fmaxf(oa + bias2, 0.f);
                out[row + q + 8] = fmaxf(ob + bias2, 0.f);
            }
        }

        __syncthreads();   // all reads of buf[sb] done; prefetch STS visible
    }
}

// ---------------------------------------------------------------------------
extern "C" void kernel_launch(void* const* d_in, const int* in_sizes, int n_in,
                              void* d_out, int out_size)
{
    const float* x     = (const float*)d_in[0];
    const float* y     = (const float*)d_in[1];
    const float* W1    = (const float*)d_in[2];
    const float* b1    = (const float*)d_in[3];
    const float* gamma = (const float*)d_in[4];
    const float* beta  = (const float*)d_in[5];
    const float* W2    = (const float*)d_in[6];
    const float* b2    = (const float*)d_in[7];
    float* out = (float*)d_out;

    cudaFuncSetAttribute(main_kernel,
                         cudaFuncAttributeMaxDynamicSharedMemorySize, SMEM_BYTES);

    precompute_kernel<<<512, 128>>>(x, y, W1, b1);
    main_kernel<<<GRID, THREADS, SMEM_BYTES>>>(x, y, W1, gamma, beta, W2, b2, out);
}

// round 6
// speedup vs baseline: 8.1328x; 1.2153x over previous
#include <cuda_runtime.h>
#include <cuda_fp16.h>
#include <cstdint>

#define EPS 1e-5f
#define B_  4
#define N_  512
#define M_  512
#define D_  128
#define H_  128
#define TN 8
#define TM 32
#define NTILES 4096          // 4 * 64 * 16
#define GRID 148
#define THREADS 256

// SMEM byte offsets
#define SM_W    0                      // fp16 W1d^T [h][k], swizzled, 32768 B
#define SM_XS   32768                  // 2 x 8*128*4   = 2 x 4096
#define SM_YS   (SM_XS + 8192)         // 2 x 32*136*4  = 2 x 17408
#define SM_XWS  (SM_YS + 34816)        // 2 x 4096
#define SM_YWS  (SM_XWS + 8192)        // 2 x 17408
#define SM_GAM  (SM_YWS + 34816)
#define SM_BET  (SM_GAM + 512)
#define SM_W2   (SM_BET + 512)
#define SMEM_BYTES (SM_W2 + 512)

#define YSTRIDE 136   // floats per y-row (bank-conflict-free for (q,c) access)

__device__ __forceinline__ uint32_t smem_u32(const void* p) {
    uint32_t a;
    asm("{ .reg .u64 t; cvta.to.shared.u64 t, %1; cvt.u32.u64 %0, t; }" : "=r"(a) : "l"(p));
    return a;
}
__device__ __forceinline__ void ldsm4(uint32_t* r, uint32_t addr) {
    asm volatile("ldmatrix.sync.aligned.m8n8.x4.shared.b16 {%0,%1,%2,%3}, [%4];"
        : "=r"(r[0]), "=r"(r[1]), "=r"(r[2]), "=r"(r[3]) : "r"(addr));
}
__device__ __forceinline__ void mma16816(float* c, const uint32_t* a,
                                         uint32_t b0, uint32_t b1) {
    asm volatile("mma.sync.aligned.m16n8k16.row.col.f32.f16.f16.f32 "
        "{%0,%1,%2,%3}, {%4,%5,%6,%7}, {%8,%9}, {%0,%1,%2,%3};"
        : "+f"(c[0]), "+f"(c[1]), "+f"(c[2]), "+f"(c[3])
        : "r"(a[0]), "r"(a[1]), "r"(a[2]), "r"(a[3]), "r"(b0), "r"(b1));
}
// swizzled offset into a [rows][128] fp16 tile (256 B/row, 16B-chunk XOR swizzle)
__device__ __forceinline__ uint32_t woff(int r, int k) {
    return (uint32_t)(r * 256 + ((((k >> 3) ^ (r & 7)) << 4)) + (k & 7) * 2);
}
__device__ __forceinline__ uint32_t h2u(__half2 h) {
    return *reinterpret_cast<uint32_t*>(&h);
}

// Scratch: xw = x@W1x + b1 (b1 ONLY here), yw = y@W1y
__device__ float g_xw[B_ * N_ * H_];
__device__ float g_yw[B_ * M_ * H_];

// ---------------------------------------------------------------------------
// Kernel 1: precompute xw/yw (fp32 exact)
// ---------------------------------------------------------------------------
__global__ __launch_bounds__(128) void precompute_kernel(
    const float* __restrict__ x, const float* __restrict__ y,
    const float* __restrict__ W1, const float* __restrict__ b1)
{
    const bool isY = blockIdx.x >= 256;
    const int r0 = (isY ? blockIdx.x - 256 : blockIdx.x) * 8;
    const float* __restrict__ src = isY ? y : x;
    const float* __restrict__ W = W1 + (isY ? D_ * H_ : 0);
    float* __restrict__ dst = isY ? g_yw : g_xw;

    __shared__ float v[8][D_];
    const int h = threadIdx.x;
    #pragma unroll
    for (int r = 0; r < 8; r++) v[r][h] = src[(r0 + r) * D_ + h];
    __syncthreads();

    float acc[8];
    const float bb = isY ? 0.f : b1[h];
    #pragma unroll
    for (int r = 0; r < 8; r++) acc[r] = bb;
    #pragma unroll 4
    for (int d = 0; d < D_; d++) {
        const float w = W[d * H_ + h];
        #pragma unroll
        for (int r = 0; r < 8; r++) acc[r] = fmaf(v[r][d], w, acc[r]);
    }
    #pragma unroll
    for (int r = 0; r < 8; r++) dst[(r0 + r) * H_ + h] = acc[r];
}

// ---------------------------------------------------------------------------
// Kernel 2: persistent HMMA kernel.
// Tile = 256 pairs (8n x 32m) x 128 h, K = 128. Each warp: 1 n-row, 32 m's
// as two m16 fragment sets -> each LDSM'd B fragment feeds 4 HMMAs.
// ---------------------------------------------------------------------------
__global__ void __launch_bounds__(THREADS, 1) main_kernel(
    const float* __restrict__ x, const float* __restrict__ y,
    const float* __restrict__ W1,
    const float* __restrict__ gamma, const float* __restrict__ beta,
    const float* __restrict__ W2, const float* __restrict__ b2,
    float* __restrict__ out)
{
    extern __shared__ char sm[];
    const int tid = threadIdx.x;
    const int wid = tid >> 5, lane = tid & 31;
    const int q = lane >> 2, c = lane & 3;

    // ---- one-time: W1d -> fp16 Wsm[h][k] swizzled ----
    {
        __half* wp = (__half*)sm;
        #pragma unroll
        for (int i = 0; i < 64; i++) {
            int e = i * 256 + tid;
            int k = e >> 7, h = e & 127;
            float v = W1[(2 * D_ + k) * H_ + h];
            *reinterpret_cast<__half*>((char*)wp + woff(h, k)) = __float2half_rn(v);
        }
    }
    if (tid < 128) {
        ((float*)(sm + SM_GAM))[tid] = gamma[tid];
        ((float*)(sm + SM_BET))[tid] = beta[tid];
        ((float*)(sm + SM_W2))[tid]  = W2[tid];
    }
    const float bias2 = b2[0];

    // per-lane ldmatrix B addressing constants
    const uint32_t wbase = smem_u32(sm);
    const int rp  = (((lane >> 4) & 1) << 3) + (lane & 7);
    const int kb8 = (lane >> 3) & 1;
    const int l7  = lane & 7;

    // tile loader (LDG + STS); safe to call while other buffer is in use
    auto load_tile = [&](int t, int sb) {
        const int bt = t >> 10, rem = t & 1023;
        const int n0 = (rem >> 4) * TN, m0 = (rem & 15) * TM;
        const float4* xg  = (const float4*)(x + (bt * N_ + n0) * D_);
        const float4* xwg = (const float4*)(g_xw + (bt * N_ + n0) * H_);
        float4* xsb  = (float4*)(sm + SM_XS  + sb * 4096);
        float4* xwsb = (float4*)(sm + SM_XWS + sb * 4096);
        xsb[tid]  = xg[tid];
        xwsb[tid] = xwg[tid];
        const float* yg  = y + (bt * M_ + m0) * D_;
        const float* ywg = g_yw + (bt * M_ + m0) * H_;
        float* ysb  = (float*)(sm + SM_YS  + sb * 17408);
        float* ywsb = (float*)(sm + SM_YWS + sb * 17408);
        #pragma unroll
        for (int j = 0; j < 4; j++) {
            int e = j * 256 + tid;
            int r = e >> 5, c4 = (e & 31) * 4;
            *(float4*)(ysb  + r * YSTRIDE + c4) = *(const float4*)(yg  + r * 128 + c4);
            *(float4*)(ywsb + r * YSTRIDE + c4) = *(const float4*)(ywg + r * 128 + c4);
        }
    };

    load_tile(blockIdx.x, 0);
    __syncthreads();

    int iter = 0;
    for (int t = blockIdx.x; t < NTILES; t += GRID, iter++) {
        const int sb = iter & 1;
        const int bt = t >> 10, rem = t & 1023;
        const int n0 = (rem >> 4) * TN, m0 = (rem & 15) * TM;

        float acc[2][16][4];
        #pragma unroll
        for (int s = 0; s < 2; s++)
            #pragma unroll
            for (int i = 0; i < 16; i++)
                #pragma unroll
                for (int j = 0; j < 4; j++) acc[s][i][j] = 0.f;

        const float* xr  = (const float*)(sm + SM_XS + sb * 4096) + wid * 128;
        const float* yr0 = (const float*)(sm + SM_YS + sb * 17408) + q * YSTRIDE;

        #pragma unroll
        for (int kt = 0; kt < 8; kt++) {
            const int k0 = kt * 16 + 2 * c;
            // ---- A-gen: fp16 fragments for both m16 sets (this kt) ----
            uint32_t af[2][4];
            {
                float2 x0 = *(const float2*)(xr + k0);
                float2 x1 = *(const float2*)(xr + k0 + 8);
                #pragma unroll
                for (int s = 0; s < 2; s++) {
                    const float* ya = yr0 + (16 * s) * YSTRIDE;
                    const float* yb = ya + 8 * YSTRIDE;
                    float2 a0 = *(const float2*)(ya + k0);
                    float2 a1 = *(const float2*)(ya + k0 + 8);
                    float2 b0 = *(const float2*)(yb + k0);
                    float2 b1 = *(const float2*)(yb + k0 + 8);
                    af[s][0] = h2u(__floats2half2_rn(fabsf(x0.x - a0.x), fabsf(x0.y - a0.y)));
                    af[s][1] = h2u(__floats2half2_rn(fabsf(x0.x - b0.x), fabsf(x0.y - b0.y)));
                    af[s][2] = h2u(__floats2half2_rn(fabsf(x1.x - a1.x), fabsf(x1.y - a1.y)));
                    af[s][3] = h2u(__floats2half2_rn(fabsf(x1.x - b1.x), fabsf(x1.y - b1.y)));
                }
            }
            // ---- B fragments (one LDSM set feeds 4 HMMAs) ----
            uint32_t br[8][4];
            #pragma unroll
            for (int nt2 = 0; nt2 < 8; nt2++) {
                uint32_t addr = wbase + (uint32_t)((nt2 * 16 + rp) * 256)
                              + (uint32_t)((((2 * kt + kb8) ^ l7) << 4));
                ldsm4(br[nt2], addr);
            }
            #pragma unroll
            for (int nt2 = 0; nt2 < 8; nt2++) {
                mma16816(acc[0][2*nt2],   af[0], br[nt2][0], br[nt2][1]);
                mma16816(acc[0][2*nt2+1], af[0], br[nt2][2], br[nt2][3]);
                mma16816(acc[1][2*nt2],   af[1], br[nt2][0], br[nt2][1]);
                mma16816(acc[1][2*nt2+1], af[1], br[nt2][2], br[nt2][3]);
            }
        }

        // ---- prefetch next tile (other buffer) ----
        if (t + GRID < NTILES) load_tile(t + GRID, sb ^ 1);

        // ---- epilogue: 4 m-groups per thread (q, q+8, q+16, q+24) ----
        {
            const float* xwr = (const float*)(sm + SM_XWS + sb * 4096) + wid * 128;
            const float* ywr = (const float*)(sm + SM_YWS + sb * 17408) + q * YSTRIDE;
            const float* gm  = (const float*)(sm + SM_GAM);
            const float* be  = (const float*)(sm + SM_BET);
            const float* w2s = (const float*)(sm + SM_W2);
            const int row = (bt * N_ + n0 + wid) * M_ + m0;

            #pragma unroll
            for (int g = 0; g < 4; g++) {
                const int s = g >> 1;           // acc set
                const int hi = (g & 1) << 1;    // 0 -> regs 0,1 ; 1 -> regs 2,3
                const float* yw = ywr + 8 * g * YSTRIDE;
                float s1 = 0.f, s2 = 0.f;
                float vv[16][2];
                #pragma unroll
                for (int nt = 0; nt < 16; nt++) {
                    const int h = nt * 8 + 2 * c;
                    float2 xw2 = *(const float2*)(xwr + h);
                    float2 yw2 = *(const float2*)(yw + h);
                    float v0 = acc[s][nt][hi]     + xw2.x + yw2.x;
                    float v1 = acc[s][nt][hi + 1] + xw2.y + yw2.y;
                    vv[nt][0] = v0; vv[nt][1] = v1;
                    s1 += v0 + v1;
                    s2 = fmaf(v0, v0, fmaf(v1, v1, s2));
                }
                #pragma unroll
                for (int o = 1; o <= 2; o <<= 1) {
                    s1 += __shfl_xor_sync(0xffffffffu, s1, o);
                    s2 += __shfl_xor_sync(0xffffffffu, s2, o);
                }
                const float mu = s1 * (1.f / 128.f);
                const float rs = rsqrtf(s2 * (1.f / 128.f) - mu * mu + EPS);
                float o2 = 0.f;
                #pragma unroll
                for (int nt = 0; nt < 16; nt++) {
                    const int h = nt * 8 + 2 * c;
                    float2 g2  = *(const float2*)(gm + h);
                    float2 be2 = *(const float2*)(be + h);
                    float2 w22 = *(const float2*)(w2s + h);
                    float tv;
                    tv = fmaf((vv[nt][0] - mu) * rs, g2.x, be2.x);
                    o2 = fmaf(fmaxf(tv, 0.f), w22.x, o2);
                    tv = fmaf((vv[nt][1] - mu) * rs, g2.y, be2.y);
                    o2 = fmaf(fmaxf(tv, 0.f), w22.y, o2);
                }
                #pragma unroll
                for (int o = 1; o <= 2; o <<= 1)
                    o2 += __shfl_xor_sync(0xffffffffu, o2, o);
                if (c == 0)
                    out[row + q + 8 * g] = fmaxf(o2 + bias2, 0.f);
            }
        }

        __syncthreads();   // all reads of buf[sb] done; prefetch STS visible
    }
}

// ---------------------------------------------------------------------------
extern "C" void kernel_launch(void* const* d_in, const int* in_sizes, int n_in,
                              void* d_out, int out_size)
{
    const float* x     = (const float*)d_in[0];
    const float* y     = (const float*)d_in[1];
    const float* W1    = (const float*)d_in[2];
    const float* b1    = (const float*)d_in[3];
    const float* gamma = (const float*)d_in[4];
    const float* beta  = (const float*)d_in[5];
    const float* W2    = (const float*)d_in[6];
    const float* b2    = (const float*)d_in[7];
    float* out = (float*)d_out;

    cudaFuncSetAttribute(main_kernel,
                         cudaFuncAttributeMaxDynamicSharedMemorySize, SMEM_BYTES);

    precompute_kernel<<<512, 128>>>(x, y, W1, b1);
    main_kernel<<<GRID, THREADS, SMEM_BYTES>>>(x, y, W1, gamma, beta, W2, b2, out);
}

// round 7
// speedup vs baseline: 8.2368x; 1.0128x over previous
#include <cuda_runtime.h>
#include <cuda_fp16.h>
#include <cstdint>

#define EPS 1e-5f
#define B_  4
#define N_  512
#define M_  512
#define D_  128
#define H_  128
#define TN 8
#define TM 32
#define NTILES 4096          // 4 * 64 * 16
#define GRID 148
#define THREADS 256

// SMEM byte offsets
#define SM_W    0                      // fp16 W1d^T [h][k], swizzled, 32768 B
#define SM_XS   32768                  // 2 x 8*128*4   = 2 x 4096
#define SM_YS   (SM_XS + 8192)         // 2 x 32*136*4  = 2 x 17408
#define SM_XWS  (SM_YS + 34816)        // 2 x 4096
#define SM_YWS  (SM_XWS + 8192)        // 2 x 17408
#define SM_GAM  (SM_YWS + 34816)
#define SM_BET  (SM_GAM + 512)
#define SM_W2   (SM_BET + 512)
#define SMEM_BYTES (SM_W2 + 512)

#define YSTRIDE 136   // floats per y-row (hits the 2-wavefront LDS.64 floor)

__device__ __forceinline__ uint32_t smem_u32(const void* p) {
    uint32_t a;
    asm("{ .reg .u64 t; cvta.to.shared.u64 t, %1; cvt.u32.u64 %0, t; }" : "=r"(a) : "l"(p));
    return a;
}
__device__ __forceinline__ void ldsm4(uint32_t* r, uint32_t addr) {
    asm volatile("ldmatrix.sync.aligned.m8n8.x4.shared.b16 {%0,%1,%2,%3}, [%4];"
        : "=r"(r[0]), "=r"(r[1]), "=r"(r[2]), "=r"(r[3]) : "r"(addr));
}
__device__ __forceinline__ void mma16816(float* c, const uint32_t* a,
                                         uint32_t b0, uint32_t b1) {
    asm volatile("mma.sync.aligned.m16n8k16.row.col.f32.f16.f16.f32 "
        "{%0,%1,%2,%3}, {%4,%5,%6,%7}, {%8,%9}, {%0,%1,%2,%3};"
        : "+f"(c[0]), "+f"(c[1]), "+f"(c[2]), "+f"(c[3])
        : "r"(a[0]), "r"(a[1]), "r"(a[2]), "r"(a[3]), "r"(b0), "r"(b1));
}
// swizzled offset into a [rows][128] fp16 tile (256 B/row, 16B-chunk XOR swizzle)
__device__ __forceinline__ uint32_t woff(int r, int k) {
    return (uint32_t)(r * 256 + ((((k >> 3) ^ (r & 7)) << 4)) + (k & 7) * 2);
}
__device__ __forceinline__ uint32_t h2u(__half2 h) {
    return *reinterpret_cast<uint32_t*>(&h);
}
// |v| on the ALU pipe (sign-bit AND), keeping FABS off the FMA pipe
__device__ __forceinline__ float fabs_alu(float v) {
    return __int_as_float(__float_as_int(v) & 0x7fffffff);
}

// Scratch: xw = x@W1x + b1 (b1 ONLY here), yw = y@W1y
__device__ float g_xw[B_ * N_ * H_];
__device__ float g_yw[B_ * M_ * H_];

// ---------------------------------------------------------------------------
// Kernel 1: precompute xw/yw (fp32 exact)
// ---------------------------------------------------------------------------
__global__ __launch_bounds__(128) void precompute_kernel(
    const float* __restrict__ x, const float* __restrict__ y,
    const float* __restrict__ W1, const float* __restrict__ b1)
{
    const bool isY = blockIdx.x >= 256;
    const int r0 = (isY ? blockIdx.x - 256 : blockIdx.x) * 8;
    const float* __restrict__ src = isY ? y : x;
    const float* __restrict__ W = W1 + (isY ? D_ * H_ : 0);
    float* __restrict__ dst = isY ? g_yw : g_xw;

    __shared__ float v[8][D_];
    const int h = threadIdx.x;
    #pragma unroll
    for (int r = 0; r < 8; r++) v[r][h] = src[(r0 + r) * D_ + h];
    __syncthreads();

    float acc[8];
    const float bb = isY ? 0.f : b1[h];
    #pragma unroll
    for (int r = 0; r < 8; r++) acc[r] = bb;
    #pragma unroll 4
    for (int d = 0; d < D_; d++) {
        const float w = W[d * H_ + h];
        #pragma unroll
        for (int r = 0; r < 8; r++) acc[r] = fmaf(v[r][d], w, acc[r]);
    }
    #pragma unroll
    for (int r = 0; r < 8; r++) dst[(r0 + r) * H_ + h] = acc[r];
}

// ---------------------------------------------------------------------------
// Kernel 2: persistent HMMA kernel.
// Tile = 256 pairs (8n x 32m) x 128 h, K = 128. Each warp: 1 n-row, 32 m's
// as two m16 fragment sets -> each LDSM'd B fragment feeds 4 HMMAs.
// ---------------------------------------------------------------------------
__global__ void __launch_bounds__(THREADS, 1) main_kernel(
    const float* __restrict__ x, const float* __restrict__ y,
    const float* __restrict__ W1,
    const float* __restrict__ gamma, const float* __restrict__ beta,
    const float* __restrict__ W2, const float* __restrict__ b2,
    float* __restrict__ out)
{
    extern __shared__ char sm[];
    const int tid = threadIdx.x;
    const int wid = tid >> 5, lane = tid & 31;
    const int q = lane >> 2, c = lane & 3;

    // ---- one-time: W1d -> fp16 Wsm[h][k] swizzled ----
    {
        __half* wp = (__half*)sm;
        #pragma unroll
        for (int i = 0; i < 64; i++) {
            int e = i * 256 + tid;
            int k = e >> 7, h = e & 127;
            float v = W1[(2 * D_ + k) * H_ + h];
            *reinterpret_cast<__half*>((char*)wp + woff(h, k)) = __float2half_rn(v);
        }
    }
    if (tid < 128) {
        ((float*)(sm + SM_GAM))[tid] = gamma[tid];
        ((float*)(sm + SM_BET))[tid] = beta[tid];
        ((float*)(sm + SM_W2))[tid]  = W2[tid];
    }
    const float bias2 = b2[0];

    // per-lane ldmatrix B addressing constants
    const uint32_t wbase = smem_u32(sm);
    const int rp  = (((lane >> 4) & 1) << 3) + (lane & 7);
    const int kb8 = (lane >> 3) & 1;
    const int l7  = lane & 7;

    // tile loader (LDG + STS); safe to call while other buffer is in use
    auto load_tile = [&](int t, int sb) {
        const int bt = t >> 10, rem = t & 1023;
        const int n0 = (rem >> 4) * TN, m0 = (rem & 15) * TM;
        const float4* xg  = (const float4*)(x + (bt * N_ + n0) * D_);
        const float4* xwg = (const float4*)(g_xw + (bt * N_ + n0) * H_);
        float4* xsb  = (float4*)(sm + SM_XS  + sb * 4096);
        float4* xwsb = (float4*)(sm + SM_XWS + sb * 4096);
        xsb[tid]  = xg[tid];
        xwsb[tid] = xwg[tid];
        const float* yg  = y + (bt * M_ + m0) * D_;
        const float* ywg = g_yw + (bt * M_ + m0) * H_;
        float* ysb  = (float*)(sm + SM_YS  + sb * 17408);
        float* ywsb = (float*)(sm + SM_YWS + sb * 17408);
        #pragma unroll
        for (int j = 0; j < 4; j++) {
            int e = j * 256 + tid;
            int r = e >> 5, c4 = (e & 31) * 4;
            *(float4*)(ysb  + r * YSTRIDE + c4) = *(const float4*)(yg  + r * 128 + c4);
            *(float4*)(ywsb + r * YSTRIDE + c4) = *(const float4*)(ywg + r * 128 + c4);
        }
    };

    load_tile(blockIdx.x, 0);
    __syncthreads();

    int iter = 0;
    for (int t = blockIdx.x; t < NTILES; t += GRID, iter++) {
        const int sb = iter & 1;
        const int bt = t >> 10, rem = t & 1023;
        const int n0 = (rem >> 4) * TN, m0 = (rem & 15) * TM;

        float acc[2][16][4];
        #pragma unroll
        for (int s = 0; s < 2; s++)
            #pragma unroll
            for (int i = 0; i < 16; i++)
                #pragma unroll
                for (int j = 0; j < 4; j++) acc[s][i][j] = 0.f;

        const float* xr  = (const float*)(sm + SM_XS + sb * 4096) + wid * 128;
        const float* yr0 = (const float*)(sm + SM_YS + sb * 17408) + q * YSTRIDE;

        #pragma unroll
        for (int kt = 0; kt < 8; kt++) {
            const int k0 = kt * 16 + 2 * c;
            // ---- A-gen: fp16 fragments for both m16 sets (this kt) ----
            uint32_t af[2][4];
            {
                float2 x0 = *(const float2*)(xr + k0);
                float2 x1 = *(const float2*)(xr + k0 + 8);
                #pragma unroll
                for (int s = 0; s < 2; s++) {
                    const float* ya = yr0 + (16 * s) * YSTRIDE;
                    const float* yb = ya + 8 * YSTRIDE;
                    float2 a0 = *(const float2*)(ya + k0);
                    float2 a1 = *(const float2*)(ya + k0 + 8);
                    float2 b0 = *(const float2*)(yb + k0);
                    float2 b1 = *(const float2*)(yb + k0 + 8);
                    af[s][0] = h2u(__floats2half2_rn(fabs_alu(x0.x - a0.x), fabs_alu(x0.y - a0.y)));
                    af[s][1] = h2u(__floats2half2_rn(fabs_alu(x0.x - b0.x), fabs_alu(x0.y - b0.y)));
                    af[s][2] = h2u(__floats2half2_rn(fabs_alu(x1.x - a1.x), fabs_alu(x1.y - a1.y)));
                    af[s][3] = h2u(__floats2half2_rn(fabs_alu(x1.x - b1.x), fabs_alu(x1.y - b1.y)));
                }
            }
            // ---- B fragments (one LDSM set feeds 4 HMMAs) ----
            uint32_t br[8][4];
            #pragma unroll
            for (int nt2 = 0; nt2 < 8; nt2++) {
                uint32_t addr = wbase + (uint32_t)((nt2 * 16 + rp) * 256)
                              + (uint32_t)((((2 * kt + kb8) ^ l7) << 4));
                ldsm4(br[nt2], addr);
            }
            #pragma unroll
            for (int nt2 = 0; nt2 < 8; nt2++) {
                mma16816(acc[0][2*nt2],   af[0], br[nt2][0], br[nt2][1]);
                mma16816(acc[0][2*nt2+1], af[0], br[nt2][2], br[nt2][3]);
                mma16816(acc[1][2*nt2],   af[1], br[nt2][0], br[nt2][1]);
                mma16816(acc[1][2*nt2+1], af[1], br[nt2][2], br[nt2][3]);
            }
        }

        // ---- prefetch next tile (other buffer) ----
        if (t + GRID < NTILES) load_tile(t + GRID, sb ^ 1);

        // ---- epilogue: two passes, acc updated in place ----
        {
            const float* xwr = (const float*)(sm + SM_XWS + sb * 4096) + wid * 128;
            const float* ywr = (const float*)(sm + SM_YWS + sb * 17408) + q * YSTRIDE;
            const float* gm  = (const float*)(sm + SM_GAM);
            const float* be  = (const float*)(sm + SM_BET);
            const float* w2s = (const float*)(sm + SM_W2);
            const int row = (bt * N_ + n0 + wid) * M_ + m0;

            // pass 1: add xw+yw in place, accumulate sums per m-group
            float s1[4] = {0.f, 0.f, 0.f, 0.f};
            float s2[4] = {0.f, 0.f, 0.f, 0.f};
            #pragma unroll
            for (int nt = 0; nt < 16; nt++) {
                const int h = nt * 8 + 2 * c;
                float2 xw2 = *(const float2*)(xwr + h);
                #pragma unroll
                for (int g = 0; g < 4; g++) {
                    const int s = g >> 1, hi = (g & 1) << 1;
                    float2 yw2 = *(const float2*)(ywr + 8 * g * YSTRIDE + h);
                    float v0 = acc[s][nt][hi]     + xw2.x + yw2.x;
                    float v1 = acc[s][nt][hi + 1] + xw2.y + yw2.y;
                    acc[s][nt][hi] = v0; acc[s][nt][hi + 1] = v1;
                    s1[g] += v0 + v1;
                    s2[g] = fmaf(v0, v0, fmaf(v1, v1, s2[g]));
                }
            }
            float mu[4], rs[4], o2[4];
            #pragma unroll
            for (int g = 0; g < 4; g++) {
                #pragma unroll
                for (int o = 1; o <= 2; o <<= 1) {
                    s1[g] += __shfl_xor_sync(0xffffffffu, s1[g], o);
                    s2[g] += __shfl_xor_sync(0xffffffffu, s2[g], o);
                }
                mu[g] = s1[g] * (1.f / 128.f);
                rs[g] = rsqrtf(s2[g] * (1.f / 128.f) - mu[g] * mu[g] + EPS);
                o2[g] = 0.f;
            }
            // pass 2: gamma/beta/W2 loaded once per nt, used by all 4 groups
            #pragma unroll
            for (int nt = 0; nt < 16; nt++) {
                const int h = nt * 8 + 2 * c;
                float2 g2  = *(const float2*)(gm + h);
                float2 be2 = *(const float2*)(be + h);
                float2 w22 = *(const float2*)(w2s + h);
                #pragma unroll
                for (int g = 0; g < 4; g++) {
                    const int s = g >> 1, hi = (g & 1) << 1;
                    float tv;
                    tv = fmaf((acc[s][nt][hi] - mu[g]) * rs[g], g2.x, be2.x);
                    o2[g] = fmaf(fmaxf(tv, 0.f), w22.x, o2[g]);
                    tv = fmaf((acc[s][nt][hi + 1] - mu[g]) * rs[g], g2.y, be2.y);
                    o2[g] = fmaf(fmaxf(tv, 0.f), w22.y, o2[g]);
                }
            }
            #pragma unroll
            for (int g = 0; g < 4; g++) {
                #pragma unroll
                for (int o = 1; o <= 2; o <<= 1)
                    o2[g] += __shfl_xor_sync(0xffffffffu, o2[g], o);
                if (c == 0)
                    out[row + q + 8 * g] = fmaxf(o2[g] + bias2, 0.f);
            }
        }

        __syncthreads();   // all reads of buf[sb] done; prefetch STS visible
    }
}

// ---------------------------------------------------------------------------
extern "C" void kernel_launch(void* const* d_in, const int* in_sizes, int n_in,
                              void* d_out, int out_size)
{
    const float* x     = (const float*)d_in[0];
    const float* y     = (const float*)d_in[1];
    const float* W1    = (const float*)d_in[2];
    const float* b1    = (const float*)d_in[3];
    const float* gamma = (const float*)d_in[4];
    const float* beta  = (const float*)d_in[5];
    const float* W2    = (const float*)d_in[6];
    const float* b2    = (const float*)d_in[7];
    float* out = (float*)d_out;

    cudaFuncSetAttribute(main_kernel,
                         cudaFuncAttributeMaxDynamicSharedMemorySize, SMEM_BYTES);

    precompute_kernel<<<512, 128>>>(x, y, W1, b1);
    main_kernel<<<GRID, THREADS, SMEM_BYTES>>>(x, y, W1, gamma, beta, W2, b2, out);
}

// round 8
// speedup vs baseline: 8.5238x; 1.0348x over previous
#include <cuda_runtime.h>
#include <cuda_fp16.h>
#include <cstdint>

#define EPS 1e-5f
#define B_  4
#define N_  512
#define M_  512
#define D_  128
#define H_  128
#define TN 8
#define TM 32
#define NTILES 4096          // 4 * 64 * 16
#define GRID 148
#define THREADS 256

// SMEM byte offsets
#define SM_W    0                      // fp16 W1d^T [h][k], swizzled, 32768 B
#define SM_XS   32768                  // fp16 x: 2 x 8*128*2   = 2 x 2048
#define SM_YS   (SM_XS + 4096)         // fp16 y: 2 x 32*136*2  = 2 x 8704
#define SM_XWS  (SM_YS + 17408)        // fp32:   2 x 4096
#define SM_YWS  (SM_XWS + 8192)        // fp32:   2 x 17408
#define SM_GAM  (SM_YWS + 34816)
#define SM_BET  (SM_GAM + 512)
#define SM_W2   (SM_BET + 512)
#define SMEM_BYTES (SM_W2 + 512)

#define YSTRIDE  136   // fp32 yw rows: floats per row
#define YSTRIDE_H 136  // fp16 y rows: halves per row (272 B -> conflict-free)

__device__ __forceinline__ uint32_t smem_u32(const void* p) {
    uint32_t a;
    asm("{ .reg .u64 t; cvta.to.shared.u64 t, %1; cvt.u32.u64 %0, t; }" : "=r"(a) : "l"(p));
    return a;
}
__device__ __forceinline__ void ldsm4(uint32_t* r, uint32_t addr) {
    asm volatile("ldmatrix.sync.aligned.m8n8.x4.shared.b16 {%0,%1,%2,%3}, [%4];"
        : "=r"(r[0]), "=r"(r[1]), "=r"(r[2]), "=r"(r[3]) : "r"(addr));
}
__device__ __forceinline__ void mma16816(float* c, const uint32_t* a,
                                         uint32_t b0, uint32_t b1) {
    asm volatile("mma.sync.aligned.m16n8k16.row.col.f32.f16.f16.f32 "
        "{%0,%1,%2,%3}, {%4,%5,%6,%7}, {%8,%9}, {%0,%1,%2,%3};"
        : "+f"(c[0]), "+f"(c[1]), "+f"(c[2]), "+f"(c[3])
        : "r"(a[0]), "r"(a[1]), "r"(a[2]), "r"(a[3]), "r"(b0), "r"(b1));
}
// swizzled offset into a [rows][128] fp16 tile (256 B/row, 16B-chunk XOR swizzle)
__device__ __forceinline__ uint32_t woff(int r, int k) {
    return (uint32_t)(r * 256 + ((((k >> 3) ^ (r & 7)) << 4)) + (k & 7) * 2);
}
__device__ __forceinline__ uint32_t h2u(__half2 h) {
    return *reinterpret_cast<uint32_t*>(&h);
}

// Scratch: xw = x@W1x + b1 (b1 ONLY here), yw = y@W1y
__device__ float g_xw[B_ * N_ * H_];
__device__ float g_yw[B_ * M_ * H_];

// ---------------------------------------------------------------------------
// Kernel 1: precompute xw/yw (fp32 exact)
// ---------------------------------------------------------------------------
__global__ __launch_bounds__(128) void precompute_kernel(
    const float* __restrict__ x, const float* __restrict__ y,
    const float* __restrict__ W1, const float* __restrict__ b1)
{
    const bool isY = blockIdx.x >= 256;
    const int r0 = (isY ? blockIdx.x - 256 : blockIdx.x) * 8;
    const float* __restrict__ src = isY ? y : x;
    const float* __restrict__ W = W1 + (isY ? D_ * H_ : 0);
    float* __restrict__ dst = isY ? g_yw : g_xw;

    __shared__ float v[8][D_];
    const int h = threadIdx.x;
    #pragma unroll
    for (int r = 0; r < 8; r++) v[r][h] = src[(r0 + r) * D_ + h];
    __syncthreads();

    float acc[8];
    const float bb = isY ? 0.f : b1[h];
    #pragma unroll
    for (int r = 0; r < 8; r++) acc[r] = bb;
    #pragma unroll 4
    for (int d = 0; d < D_; d++) {
        const float w = W[d * H_ + h];
        #pragma unroll
        for (int r = 0; r < 8; r++) acc[r] = fmaf(v[r][d], w, acc[r]);
    }
    #pragma unroll
    for (int r = 0; r < 8; r++) dst[(r0 + r) * H_ + h] = acc[r];
}

// ---------------------------------------------------------------------------
// Kernel 2: persistent HMMA kernel.
// Tile = 256 pairs (8n x 32m) x 128 h, K = 128. x/y staged in SMEM as fp16;
// A-gen is pure half2 (HSUB2 + HABS2). Each LDSM'd B fragment feeds 4 HMMAs.
// ---------------------------------------------------------------------------
__global__ void __launch_bounds__(THREADS, 1) main_kernel(
    const float* __restrict__ x, const float* __restrict__ y,
    const float* __restrict__ W1,
    const float* __restrict__ gamma, const float* __restrict__ beta,
    const float* __restrict__ W2, const float* __restrict__ b2,
    float* __restrict__ out)
{
    extern __shared__ char sm[];
    const int tid = threadIdx.x;
    const int wid = tid >> 5, lane = tid & 31;
    const int q = lane >> 2, c = lane & 3;

    // ---- one-time: W1d -> fp16 Wsm[h][k] swizzled ----
    {
        __half* wp = (__half*)sm;
        #pragma unroll
        for (int i = 0; i < 64; i++) {
            int e = i * 256 + tid;
            int k = e >> 7, h = e & 127;
            float v = W1[(2 * D_ + k) * H_ + h];
            *reinterpret_cast<__half*>((char*)wp + woff(h, k)) = __float2half_rn(v);
        }
    }
    if (tid < 128) {
        ((float*)(sm + SM_GAM))[tid] = gamma[tid];
        ((float*)(sm + SM_BET))[tid] = beta[tid];
        ((float*)(sm + SM_W2))[tid]  = W2[tid];
    }
    const float bias2 = b2[0];

    // per-lane ldmatrix B addressing constants
    const uint32_t wbase = smem_u32(sm);
    const int rp  = (((lane >> 4) & 1) << 3) + (lane & 7);
    const int kb8 = (lane >> 3) & 1;
    const int l7  = lane & 7;

    // tile loader: LDG fp32, convert, STS fp16 (x/y) + fp32 (xw/yw)
    auto load_tile = [&](int t, int sb) {
        const int bt = t >> 10, rem = t & 1023;
        const int n0 = (rem >> 4) * TN, m0 = (rem & 15) * TM;
        // x: 1024 floats -> fp16
        {
            float4 v = ((const float4*)(x + (bt * N_ + n0) * D_))[tid];
            __half2 h0 = __floats2half2_rn(v.x, v.y);
            __half2 h1 = __floats2half2_rn(v.z, v.w);
            uint2 pk = make_uint2(h2u(h0), h2u(h1));
            *(uint2*)((char*)sm + SM_XS + sb * 2048 + tid * 8) = pk;
        }
        // xw: fp32
        ((float4*)(sm + SM_XWS + sb * 4096))[tid] =
            ((const float4*)(g_xw + (bt * N_ + n0) * H_))[tid];
        // y: 4096 floats -> fp16 padded rows
        {
            const float* yg = y + (bt * M_ + m0) * D_;
            __half* ysb = (__half*)(sm + SM_YS + sb * 8704);
            #pragma unroll
            for (int j = 0; j < 4; j++) {
                int e = j * 256 + tid;
                int r = e >> 5, c4 = (e & 31) * 4;
                float4 v = *(const float4*)(yg + r * 128 + c4);
                __half2 h0 = __floats2half2_rn(v.x, v.y);
                __half2 h1 = __floats2half2_rn(v.z, v.w);
                uint2 pk = make_uint2(h2u(h0), h2u(h1));
                *(uint2*)(ysb + r * YSTRIDE_H + c4) = pk;
            }
        }
        // yw: fp32 padded rows
        {
            const float* ywg = g_yw + (bt * M_ + m0) * H_;
            float* ywsb = (float*)(sm + SM_YWS + sb * 17408);
            #pragma unroll
            for (int j = 0; j < 4; j++) {
                int e = j * 256 + tid;
                int r = e >> 5, c4 = (e & 31) * 4;
                *(float4*)(ywsb + r * YSTRIDE + c4) = *(const float4*)(ywg + r * 128 + c4);
            }
        }
    };

    load_tile(blockIdx.x, 0);
    __syncthreads();

    int iter = 0;
    for (int t = blockIdx.x; t < NTILES; t += GRID, iter++) {
        const int sb = iter & 1;
        const int bt = t >> 10, rem = t & 1023;
        const int n0 = (rem >> 4) * TN, m0 = (rem & 15) * TM;

        float acc[2][16][4];
        #pragma unroll
        for (int s = 0; s < 2; s++)
            #pragma unroll
            for (int i = 0; i < 16; i++)
                #pragma unroll
                for (int j = 0; j < 4; j++) acc[s][i][j] = 0.f;

        const __half* xr  = (const __half*)(sm + SM_XS + sb * 2048) + wid * 128;
        const __half* yr0 = (const __half*)(sm + SM_YS + sb * 8704) + q * YSTRIDE_H;

        #pragma unroll
        for (int kt = 0; kt < 8; kt++) {
            const int k0 = kt * 16 + 2 * c;
            // ---- B fragments FIRST (LDSM latency covered by A-gen below) ----
            uint32_t br[8][4];
            #pragma unroll
            for (int nt2 = 0; nt2 < 8; nt2++) {
                uint32_t addr = wbase + (uint32_t)((nt2 * 16 + rp) * 256)
                              + (uint32_t)((((2 * kt + kb8) ^ l7) << 4));
                ldsm4(br[nt2], addr);
            }
            // ---- A-gen: half2 |x - y| fragments ----
            uint32_t af[2][4];
            {
                __half2 x0 = *(const __half2*)(xr + k0);
                __half2 x1 = *(const __half2*)(xr + k0 + 8);
                #pragma unroll
                for (int s = 0; s < 2; s++) {
                    const __half* ya = yr0 + (16 * s) * YSTRIDE_H;
                    const __half* yb = ya + 8 * YSTRIDE_H;
                    __half2 a0 = *(const __half2*)(ya + k0);
                    __half2 a1 = *(const __half2*)(ya + k0 + 8);
                    __half2 b0 = *(const __half2*)(yb + k0);
                    __half2 b1 = *(const __half2*)(yb + k0 + 8);
                    af[s][0] = h2u(__habs2(__hsub2(x0, a0)));
                    af[s][1] = h2u(__habs2(__hsub2(x0, b0)));
                    af[s][2] = h2u(__habs2(__hsub2(x1, a1)));
                    af[s][3] = h2u(__habs2(__hsub2(x1, b1)));
                }
            }
            #pragma unroll
            for (int nt2 = 0; nt2 < 8; nt2++) {
                mma16816(acc[0][2*nt2],   af[0], br[nt2][0], br[nt2][1]);
                mma16816(acc[0][2*nt2+1], af[0], br[nt2][2], br[nt2][3]);
                mma16816(acc[1][2*nt2],   af[1], br[nt2][0], br[nt2][1]);
                mma16816(acc[1][2*nt2+1], af[1], br[nt2][2], br[nt2][3]);
            }
        }

        // ---- prefetch next tile (other buffer) ----
        if (t + GRID < NTILES) load_tile(t + GRID, sb ^ 1);

        // ---- epilogue: two passes, acc updated in place ----
        {
            const float* xwr = (const float*)(sm + SM_XWS + sb * 4096) + wid * 128;
            const float* ywr = (const float*)(sm + SM_YWS + sb * 17408) + q * YSTRIDE;
            const float* gm  = (const float*)(sm + SM_GAM);
            const float* be  = (const float*)(sm + SM_BET);
            const float* w2s = (const float*)(sm + SM_W2);
            const int row = (bt * N_ + n0 + wid) * M_ + m0;

            float s1[4] = {0.f, 0.f, 0.f, 0.f};
            float s2[4] = {0.f, 0.f, 0.f, 0.f};
            #pragma unroll
            for (int nt = 0; nt < 16; nt++) {
                const int h = nt * 8 + 2 * c;
                float2 xw2 = *(const float2*)(xwr + h);
                #pragma unroll
                for (int g = 0; g < 4; g++) {
                    const int s = g >> 1, hi = (g & 1) << 1;
                    float2 yw2 = *(const float2*)(ywr + 8 * g * YSTRIDE + h);
                    float v0 = acc[s][nt][hi]     + xw2.x + yw2.x;
                    float v1 = acc[s][nt][hi + 1] + xw2.y + yw2.y;
                    acc[s][nt][hi] = v0; acc[s][nt][hi + 1] = v1;
                    s1[g] += v0 + v1;
                    s2[g] = fmaf(v0, v0, fmaf(v1, v1, s2[g]));
                }
            }
            float mu[4], rs[4], o2[4];
            #pragma unroll
            for (int g = 0; g < 4; g++) {
                #pragma unroll
                for (int o = 1; o <= 2; o <<= 1) {
                    s1[g] += __shfl_xor_sync(0xffffffffu, s1[g], o);
                    s2[g] += __shfl_xor_sync(0xffffffffu, s2[g], o);
                }
                mu[g] = s1[g] * (1.f / 128.f);
                rs[g] = rsqrtf(s2[g] * (1.f / 128.f) - mu[g] * mu[g] + EPS);
                o2[g] = 0.f;
            }
            #pragma unroll
            for (int nt = 0; nt < 16; nt++) {
                const int h = nt * 8 + 2 * c;
                float2 g2  = *(const float2*)(gm + h);
                float2 be2 = *(const float2*)(be + h);
                float2 w22 = *(const float2*)(w2s + h);
                #pragma unroll
                for (int g = 0; g < 4; g++) {
                    const int s = g >> 1, hi = (g & 1) << 1;
                    float tv;
                    tv = fmaf((acc[s][nt][hi] - mu[g]) * rs[g], g2.x, be2.x);
                    o2[g] = fmaf(fmaxf(tv, 0.f), w22.x, o2[g]);
                    tv = fmaf((acc[s][nt][hi + 1] - mu[g]) * rs[g], g2.y, be2.y);
                    o2[g] = fmaf(fmaxf(tv, 0.f), w22.y, o2[g]);
                }
            }
            #pragma unroll
            for (int g = 0; g < 4; g++) {
                #pragma unroll
                for (int o = 1; o <= 2; o <<= 1)
                    o2[g] += __shfl_xor_sync(0xffffffffu, o2[g], o);
                if (c == 0)
                    out[row + q + 8 * g] = fmaxf(o2[g] + bias2, 0.f);
            }
        }

        __syncthreads();   // all reads of buf[sb] done; prefetch STS visible
    }
}

// ---------------------------------------------------------------------------
extern "C" void kernel_launch(void* const* d_in, const int* in_sizes, int n_in,
                              void* d_out, int out_size)
{
    const float* x     = (const float*)d_in[0];
    const float* y     = (const float*)d_in[1];
    const float* W1    = (const float*)d_in[2];
    const float* b1    = (const float*)d_in[3];
    const float* gamma = (const float*)d_in[4];
    const float* beta  = (const float*)d_in[5];
    const float* W2    = (const float*)d_in[6];
    const float* b2    = (const float*)d_in[7];
    float* out = (float*)d_out;

    cudaFuncSetAttribute(main_kernel,
                         cudaFuncAttributeMaxDynamicSharedMemorySize, SMEM_BYTES);

    precompute_kernel<<<512, 128>>>(x, y, W1, b1);
    main_kernel<<<GRID, THREADS, SMEM_BYTES>>>(x, y, W1, gamma, beta, W2, b2, out);
}

// round 9
// speedup vs baseline: 8.5978x; 1.0087x over previous
#include <cuda_runtime.h>
#include <cuda_fp16.h>
#include <cstdint>

#define EPS 1e-5f
#define B_  4
#define N_  512
#define M_  512
#define D_  128
#define H_  128
#define TN 8
#define TM 32
#define NTILES 4096          // 4 * 64 * 16
#define GRID 148
#define THREADS 256

// SMEM byte offsets
#define SM_W    0                      // fp16 W1d^T [h][k], swizzled, 32768 B
#define SM_XS   32768                  // fp16 x: 2 x 8*128*2   = 2 x 2048
#define SM_YS   (SM_XS + 4096)         // fp16 y: 2 x 32*136*2  = 2 x 8704
#define SM_XWS  (SM_YS + 17408)        // fp32:   2 x 4096
#define SM_YWS  (SM_XWS + 8192)        // fp32:   2 x 17408
#define SM_GAM  (SM_YWS + 34816)
#define SM_BET  (SM_GAM + 512)
#define SM_W2   (SM_BET + 512)
#define SMEM_BYTES (SM_W2 + 512)

#define YSTRIDE  136   // fp32 yw rows: floats per row
#define YSTRIDE_H 136  // fp16 y rows: halves per row

__device__ __forceinline__ uint32_t smem_u32(const void* p) {
    uint32_t a;
    asm("{ .reg .u64 t; cvta.to.shared.u64 t, %1; cvt.u32.u64 %0, t; }" : "=r"(a) : "l"(p));
    return a;
}
__device__ __forceinline__ void ldsm4(uint32_t* r, uint32_t addr) {
    asm volatile("ldmatrix.sync.aligned.m8n8.x4.shared.b16 {%0,%1,%2,%3}, [%4];"
        : "=r"(r[0]), "=r"(r[1]), "=r"(r[2]), "=r"(r[3]) : "r"(addr));
}
__device__ __forceinline__ void mma16816(float* c, const uint32_t* a,
                                         uint32_t b0, uint32_t b1) {
    asm volatile("mma.sync.aligned.m16n8k16.row.col.f32.f16.f16.f32 "
        "{%0,%1,%2,%3}, {%4,%5,%6,%7}, {%8,%9}, {%0,%1,%2,%3};"
        : "+f"(c[0]), "+f"(c[1]), "+f"(c[2]), "+f"(c[3])
        : "r"(a[0]), "r"(a[1]), "r"(a[2]), "r"(a[3]), "r"(b0), "r"(b1));
}
// swizzled offset into a [rows][128] fp16 tile (256 B/row, 16B-chunk XOR swizzle)
__device__ __forceinline__ uint32_t woff(int r, int k) {
    return (uint32_t)(r * 256 + ((((k >> 3) ^ (r & 7)) << 4)) + (k & 7) * 2);
}
__device__ __forceinline__ uint32_t h2u(__half2 h) {
    return *reinterpret_cast<uint32_t*>(&h);
}

// Scratch: xw = x@W1x + b1 (b1 ONLY here), yw = y@W1y
__device__ float g_xw[B_ * N_ * H_];
__device__ float g_yw[B_ * M_ * H_];

// ---------------------------------------------------------------------------
// Kernel 1: precompute xw/yw (fp32 exact)
// ---------------------------------------------------------------------------
__global__ __launch_bounds__(128) void precompute_kernel(
    const float* __restrict__ x, const float* __restrict__ y,
    const float* __restrict__ W1, const float* __restrict__ b1)
{
    const bool isY = blockIdx.x >= 256;
    const int r0 = (isY ? blockIdx.x - 256 : blockIdx.x) * 8;
    const float* __restrict__ src = isY ? y : x;
    const float* __restrict__ W = W1 + (isY ? D_ * H_ : 0);
    float* __restrict__ dst = isY ? g_yw : g_xw;

    __shared__ float v[8][D_];
    const int h = threadIdx.x;
    #pragma unroll
    for (int r = 0; r < 8; r++) v[r][h] = src[(r0 + r) * D_ + h];
    __syncthreads();

    float acc[8];
    const float bb = isY ? 0.f : b1[h];
    #pragma unroll
    for (int r = 0; r < 8; r++) acc[r] = bb;
    #pragma unroll 4
    for (int d = 0; d < D_; d++) {
        const float w = W[d * H_ + h];
        #pragma unroll
        for (int r = 0; r < 8; r++) acc[r] = fmaf(v[r][d], w, acc[r]);
    }
    #pragma unroll
    for (int r = 0; r < 8; r++) dst[(r0 + r) * H_ + h] = acc[r];
}

// ---------------------------------------------------------------------------
// Kernel 2: persistent HMMA kernel, software-pipelined mainloop.
// Tile = 256 pairs (8n x 32m) x 128 h, K = 128.
// ---------------------------------------------------------------------------
__global__ void __launch_bounds__(THREADS, 1) main_kernel(
    const float* __restrict__ x, const float* __restrict__ y,
    const float* __restrict__ W1,
    const float* __restrict__ gamma, const float* __restrict__ beta,
    const float* __restrict__ W2, const float* __restrict__ b2,
    float* __restrict__ out)
{
    extern __shared__ char sm[];
    const int tid = threadIdx.x;
    const int wid = tid >> 5, lane = tid & 31;
    const int q = lane >> 2, c = lane & 3;

    // ---- one-time: W1d -> fp16 Wsm[h][k] swizzled ----
    {
        __half* wp = (__half*)sm;
        #pragma unroll
        for (int i = 0; i < 64; i++) {
            int e = i * 256 + tid;
            int k = e >> 7, h = e & 127;
            float v = W1[(2 * D_ + k) * H_ + h];
            *reinterpret_cast<__half*>((char*)wp + woff(h, k)) = __float2half_rn(v);
        }
    }
    if (tid < 128) {
        ((float*)(sm + SM_GAM))[tid] = gamma[tid];
        ((float*)(sm + SM_BET))[tid] = beta[tid];
        ((float*)(sm + SM_W2))[tid]  = W2[tid];
    }
    const float bias2 = b2[0];

    // per-lane ldmatrix B addressing constants
    const uint32_t wbase = smem_u32(sm);
    const int rp  = (((lane >> 4) & 1) << 3) + (lane & 7);
    const int kb8 = (lane >> 3) & 1;
    const int l7  = lane & 7;

    // tile loader: LDG fp32, convert, STS fp16 (x/y) + fp32 (xw/yw)
    auto load_tile = [&](int t, int sb) {
        const int bt = t >> 10, rem = t & 1023;
        const int n0 = (rem >> 4) * TN, m0 = (rem & 15) * TM;
        {
            float4 v = ((const float4*)(x + (bt * N_ + n0) * D_))[tid];
            __half2 h0 = __floats2half2_rn(v.x, v.y);
            __half2 h1 = __floats2half2_rn(v.z, v.w);
            uint2 pk = make_uint2(h2u(h0), h2u(h1));
            *(uint2*)((char*)sm + SM_XS + sb * 2048 + tid * 8) = pk;
        }
        ((float4*)(sm + SM_XWS + sb * 4096))[tid] =
            ((const float4*)(g_xw + (bt * N_ + n0) * H_))[tid];
        {
            const float* yg = y + (bt * M_ + m0) * D_;
            __half* ysb = (__half*)(sm + SM_YS + sb * 8704);
            #pragma unroll
            for (int j = 0; j < 4; j++) {
                int e = j * 256 + tid;
                int r = e >> 5, c4 = (e & 31) * 4;
                float4 v = *(const float4*)(yg + r * 128 + c4);
                __half2 h0 = __floats2half2_rn(v.x, v.y);
                __half2 h1 = __floats2half2_rn(v.z, v.w);
                uint2 pk = make_uint2(h2u(h0), h2u(h1));
                *(uint2*)(ysb + r * YSTRIDE_H + c4) = pk;
            }
        }
        {
            const float* ywg = g_yw + (bt * M_ + m0) * H_;
            float* ywsb = (float*)(sm + SM_YWS + sb * 17408);
            #pragma unroll
            for (int j = 0; j < 4; j++) {
                int e = j * 256 + tid;
                int r = e >> 5, c4 = (e & 31) * 4;
                *(float4*)(ywsb + r * YSTRIDE + c4) = *(const float4*)(ywg + r * 128 + c4);
            }
        }
    };

    load_tile(blockIdx.x, 0);
    __syncthreads();

    int iter = 0;
    for (int t = blockIdx.x; t < NTILES; t += GRID, iter++) {
        const int sb = iter & 1;
        const int bt = t >> 10, rem = t & 1023;
        const int n0 = (rem >> 4) * TN, m0 = (rem & 15) * TM;

        float acc[2][16][4];
        #pragma unroll
        for (int s = 0; s < 2; s++)
            #pragma unroll
            for (int i = 0; i < 16; i++)
                #pragma unroll
                for (int j = 0; j < 4; j++) acc[s][i][j] = 0.f;

        const __half* xr  = (const __half*)(sm + SM_XS + sb * 2048) + wid * 128;
        const __half* yr0 = (const __half*)(sm + SM_YS + sb * 8704) + q * YSTRIDE_H;

        // A-fragment generator for one kt into af[2][4]
        auto agen = [&](int kt, uint32_t af[2][4]) {
            const int k0 = kt * 16 + 2 * c;
            __half2 x0 = *(const __half2*)(xr + k0);
            __half2 x1 = *(const __half2*)(xr + k0 + 8);
            #pragma unroll
            for (int s = 0; s < 2; s++) {
                const __half* ya = yr0 + (16 * s) * YSTRIDE_H;
                const __half* yb = ya + 8 * YSTRIDE_H;
                __half2 a0 = *(const __half2*)(ya + k0);
                __half2 a1 = *(const __half2*)(ya + k0 + 8);
                __half2 b0 = *(const __half2*)(yb + k0);
                __half2 b1 = *(const __half2*)(yb + k0 + 8);
                af[s][0] = h2u(__habs2(__hsub2(x0, a0)));
                af[s][1] = h2u(__habs2(__hsub2(x0, b0)));
                af[s][2] = h2u(__habs2(__hsub2(x1, a1)));
                af[s][3] = h2u(__habs2(__hsub2(x1, b1)));
            }
        };
        // LDSM chunk: 4 consecutive nt2 fragments (half = 0 or 1) of one kt
        auto ldsm_chunk = [&](uint32_t br[4][4], int kt, int half) {
            const uint32_t kcol = (uint32_t)((((2 * kt + kb8) ^ l7) << 4));
            #pragma unroll
            for (int j = 0; j < 4; j++) {
                uint32_t addr = wbase + (uint32_t)(((half * 4 + j) * 16 + rp) * 256) + kcol;
                ldsm4(br[j], addr);
            }
        };

        uint32_t af[2][2][4];   // [kt&1][m-set][frag]
        uint32_t br[2][4][4];   // [chunk buf][nt2-in-chunk][frag]

        agen(0, af[0]);
        ldsm_chunk(br[0], 0, 0);

        #pragma unroll
        for (int kt = 0; kt < 8; kt++) {
            const int cb = kt & 1;
            // prefetch second half of this kt's B
            ldsm_chunk(br[1], kt, 1);
            // HMMA on first half (br[0] = nt2 0..3)
            #pragma unroll
            for (int j = 0; j < 4; j++) {
                mma16816(acc[0][2*j],   af[cb][0], br[0][j][0], br[0][j][1]);
                mma16816(acc[0][2*j+1], af[cb][0], br[0][j][2], br[0][j][3]);
                mma16816(acc[1][2*j],   af[cb][1], br[0][j][0], br[0][j][1]);
                mma16816(acc[1][2*j+1], af[cb][1], br[0][j][2], br[0][j][3]);
            }
            // under those HMMAs: next kt's A fragments + first B chunk
            if (kt < 7) {
                agen(kt + 1, af[cb ^ 1]);
                ldsm_chunk(br[0], kt + 1, 0);
            }
            // HMMA on second half (br[1] = nt2 4..7)
            #pragma unroll
            for (int j = 0; j < 4; j++) {
                const int n2 = j + 4;
                mma16816(acc[0][2*n2],   af[cb][0], br[1][j][0], br[1][j][1]);
                mma16816(acc[0][2*n2+1], af[cb][0], br[1][j][2], br[1][j][3]);
                mma16816(acc[1][2*n2],   af[cb][1], br[1][j][0], br[1][j][1]);
                mma16816(acc[1][2*n2+1], af[cb][1], br[1][j][2], br[1][j][3]);
            }
        }

        // ---- prefetch next tile (other buffer) ----
        if (t + GRID < NTILES) load_tile(t + GRID, sb ^ 1);

        // ---- epilogue: two passes, acc updated in place ----
        {
            const float* xwr = (const float*)(sm + SM_XWS + sb * 4096) + wid * 128;
            const float* ywr = (const float*)(sm + SM_YWS + sb * 17408) + q * YSTRIDE;
            const float* gm  = (const float*)(sm + SM_GAM);
            const float* be  = (const float*)(sm + SM_BET);
            const float* w2s = (const float*)(sm + SM_W2);
            const int row = (bt * N_ + n0 + wid) * M_ + m0;

            float s1[4] = {0.f, 0.f, 0.f, 0.f};
            float s2[4] = {0.f, 0.f, 0.f, 0.f};
            #pragma unroll
            for (int nt = 0; nt < 16; nt++) {
                const int h = nt * 8 + 2 * c;
                float2 xw2 = *(const float2*)(xwr + h);
                #pragma unroll
                for (int g = 0; g < 4; g++) {
                    const int s = g >> 1, hi = (g & 1) << 1;
                    float2 yw2 = *(const float2*)(ywr + 8 * g * YSTRIDE + h);
                    float v0 = acc[s][nt][hi]     + xw2.x + yw2.x;
                    float v1 = acc[s][nt][hi + 1] + xw2.y + yw2.y;
                    acc[s][nt][hi] = v0; acc[s][nt][hi + 1] = v1;
                    s1[g] += v0 + v1;
                    s2[g] = fmaf(v0, v0, fmaf(v1, v1, s2[g]));
                }
            }
            float mu[4], rs[4], o2[4];
            #pragma unroll
            for (int g = 0; g < 4; g++) {
                #pragma unroll
                for (int o = 1; o <= 2; o <<= 1) {
                    s1[g] += __shfl_xor_sync(0xffffffffu, s1[g], o);
                    s2[g] += __shfl_xor_sync(0xffffffffu, s2[g], o);
                }
                mu[g] = s1[g] * (1.f / 128.f);
                rs[g] = rsqrtf(s2[g] * (1.f / 128.f) - mu[g] * mu[g] + EPS);
                o2[g] = 0.f;
            }
            #pragma unroll
            for (int nt = 0; nt < 16; nt++) {
                const int h = nt * 8 + 2 * c;
                float2 g2  = *(const float2*)(gm + h);
                float2 be2 = *(const float2*)(be + h);
                float2 w22 = *(const float2*)(w2s + h);
                #pragma unroll
                for (int g = 0; g < 4; g++) {
                    const int s = g >> 1, hi = (g & 1) << 1;
                    float tv;
                    tv = fmaf((acc[s][nt][hi] - mu[g]) * rs[g], g2.x, be2.x);
                    o2[g] = fmaf(fmaxf(tv, 0.f), w22.x, o2[g]);
                    tv = fmaf((acc[s][nt][hi + 1] - mu[g]) * rs[g], g2.y, be2.y);
                    o2[g] = fmaf(fmaxf(tv, 0.f), w22.y, o2[g]);
                }
            }
            #pragma unroll
            for (int g = 0; g < 4; g++) {
                #pragma unroll
                for (int o = 1; o <= 2; o <<= 1)
                    o2[g] += __shfl_xor_sync(0xffffffffu, o2[g], o);
                if (c == 0)
                    out[row + q + 8 * g] = fmaxf(o2[g] + bias2, 0.f);
            }
        }

        __syncthreads();   // all reads of buf[sb] done; prefetch STS visible
    }
}

// ---------------------------------------------------------------------------
extern "C" void kernel_launch(void* const* d_in, const int* in_sizes, int n_in,
                              void* d_out, int out_size)
{
    const float* x     = (const float*)d_in[0];
    const float* y     = (const float*)d_in[1];
    const float* W1    = (const float*)d_in[2];
    const float* b1    = (const float*)d_in[3];
    const float* gamma = (const float*)d_in[4];
    const float* beta  = (const float*)d_in[5];
    const float* W2    = (const float*)d_in[6];
    const float* b2    = (const float*)d_in[7];
    float* out = (float*)d_out;

    cudaFuncSetAttribute(main_kernel,
                         cudaFuncAttributeMaxDynamicSharedMemorySize, SMEM_BYTES);

    precompute_kernel<<<512, 128>>>(x, y, W1, b1);
    main_kernel<<<GRID, THREADS, SMEM_BYTES>>>(x, y, W1, gamma, beta, W2, b2, out);
}